// round 14
// baseline (speedup 1.0000x reference)
#include <cuda_runtime.h>
#include <cuda_bf16.h>
#include <math.h>
#include <stdint.h>

constexpr int  NB   = 64;
constexpr long ROWS = 12544;

// ---------------- fp32 scratch ----------------
constexpr long O_Y=0, O_SC=O_Y+3211264, O_RE2=O_SC+2458624,
 O_PRE1=O_RE2+3211264, O_OUT=O_PRE1+3211264, O_R1=O_OUT+3211264, O_R2=O_R1+1605632,
 O_R3=O_R2+802816, O_R3T=O_R3+401408, O_PART=O_R3T+401408,
 O_RFC=O_PART+9633792,
 O_H1=O_RFC+200704, O_REX=O_H1+3211264, O_OUT1=O_REX+3211264, O_OT=O_OUT1+3211264,
 O_OFC=O_OT+3211264, O_BS1=O_OFC+65536, O_BS2=O_BS1+16384, O_MEAN=O_BS2+16384,
 O_ISTD=O_MEAN+256, O_SCAL=O_ISTD+256, O_FEND=O_SCAL+64;
__device__ float g_f[O_FEND];
__device__ int   g_pos[64];

// ---------------- bf16 scratch ([hi|lo] 2-segment layouts) ----------------
constexpr long B_ABIG=0;                                    // 16384 x 4608
constexpr long B_YAB  = B_ABIG + 75497472L;                 // 64 x 256 x 512
constexpr long B_ATT  = B_YAB  + 8388608L;
constexpr long B_YT   = B_ATT  + 8388608L;
constexpr long B_REAHL= B_YT   + 8388608L;                  // 12544 x 512
constexpr long B_OUTHL= B_REAHL+ 6422528L;                  // 12544 x 512
constexpr long B_PW   = B_OUTHL+ 6422528L;                  // 256 x 1536
constexpr long B_WO   = B_PW   + 393216L;
constexpr long B_SH   = B_WO   + 131072L;
constexpr long B_RC1  = B_SH   + 131072L;                   // 128 x 4608
constexpr long B_RC2  = B_RC1  + 589824L;
constexpr long B_RC3  = B_RC2  + 294912L;
constexpr long B_EW1  = B_RC3  + 147456L;                   // 2048 x 4608
constexpr long B_EW2  = B_EW1  + 9437184L;
constexpr long B_HEND = B_EW2  + 9437184L;
__device__ __align__(1024) __nv_bfloat16 g_h[B_HEND];

// ---------------- helpers ----------------
__device__ __forceinline__ uint32_t smem_u32(const void* p) {
    uint32_t a;
    asm("{ .reg .u64 t; cvta.to.shared.u64 t, %1; cvt.u32.u64 %0, t; }" : "=r"(a) : "l"(p));
    return a;
}
__device__ __forceinline__ float geluf(float v) {
    return 0.5f * v * (1.0f + erff(v * 0.70710678118654752440f));
}
// cg = bypass L1 (16B only) — keeps L1 free for ldmatrix traffic
#define CP_ASYNC16(dst, src) \
    asm volatile("cp.async.cg.shared.global [%0], [%1], 16;" :: "r"(dst), "l"(src))
#define CP_COMMIT() asm volatile("cp.async.commit_group;" ::: "memory")
#define CP_WAIT1()  asm volatile("cp.async.wait_group 1;" ::: "memory")
#define LDSM_X4(r, addr) \
    asm volatile("ldmatrix.sync.aligned.m8n8.x4.shared.b16 {%0,%1,%2,%3}, [%4];" \
        : "=r"((r)[0]), "=r"((r)[1]), "=r"((r)[2]), "=r"((r)[3]) : "r"(addr))
__device__ __forceinline__ void mma16816(float* c, const uint32_t* a, uint32_t b0, uint32_t b1) {
    asm volatile("mma.sync.aligned.m16n8k16.row.col.f32.bf16.bf16.f32 "
        "{%0,%1,%2,%3}, {%4,%5,%6,%7}, {%8,%9}, {%0,%1,%2,%3};"
        : "+f"(c[0]), "+f"(c[1]), "+f"(c[2]), "+f"(c[3])
        : "r"(a[0]), "r"(a[1]), "r"(a[2]), "r"(a[3]), "r"(b0), "r"(b1));
}
__device__ __forceinline__ __nv_bfloat16 pick_hl(float x, bool lo) {
    __nv_bfloat16 hi = __float2bfloat16(x);
    return lo ? __float2bfloat16(x - __bfloat162float(hi)) : hi;
}

// ---------------- tensor GEMM: 3-phase bf16x3, K-chunk 32, 3-stage ----------------
// A [Mpad][2*Kseg] = [hi|lo], B [Npad][2*Kseg] same.
// phaseSplit=0: full 3-phase accumulate + fused epilogue.
// phaseSplit=1: grid.z = 3*Z; CTA computes ONE phase, writes raw partial.
constexpr int SSTR = 40;
constexpr uint32_t BUFB = 128 * SSTR * 2;      // 10240 B
constexpr int SMEM_T = 6 * (int)BUFB;          // 61440

__global__ __launch_bounds__(256) void k_tgemm(
    const __nv_bfloat16* __restrict__ A, const __nv_bfloat16* __restrict__ Bm,
    float* __restrict__ C, float* __restrict__ Craw, __nv_bfloat16* __restrict__ CHL,
    int M, int N, int Kseg,
    long sA, long sB, long sC, long sCHL,
    const int* __restrict__ bIdx, const float* __restrict__ bias, long sBias,
    const float* __restrict__ zscale, float alpha, int act,
    const float* __restrict__ addSrc, long sAdd, int addMode, int phaseSplit)
{
    extern __shared__ __align__(16) char smem[];
    const int tid = threadIdx.x, w = tid >> 5, lane = tid & 31;
    const int zt = blockIdx.z, m0 = blockIdx.y * 128, n0 = blockIdx.x * 128;
    int zb = zt, phase = 0;
    if (phaseSplit) { zb = zt / 3; phase = zt - zb * 3; }
    const int Ka = 2 * Kseg;

    A += (long)zb * sA;
    const int bi = bIdx ? bIdx[zb] : zb;
    Bm += (long)bi * sB;
    const float* biasP = bias ? bias + (long)bi * sBias : nullptr;
    const float zs = zscale ? zscale[zb] : 1.0f;
    float* Cz  = C    ? C    + (long)zt * sC  : nullptr;
    float* Cr  = Craw ? Craw + (long)zt * sC  : nullptr;
    __nv_bfloat16* CHz = CHL ? CHL + (long)zt * sCHL : nullptr;
    const float* addP = addSrc ? addSrc + (long)zb * sAdd : nullptr;

    const uint32_t saB = smem_u32(smem);
    const uint32_t sbB = saB + 3 * BUFB;

    const int wm = w & 3, wn = w >> 2;
    const int matId = lane >> 3;
    const int aRow = wm * 32 + (matId & 1) * 8 + (lane & 7);
    const int aCol = (matId >> 1) * 8;
    const int bRow = wn * 64 + (matId >> 1) * 8 + (lane & 7);
    const int bCol = (matId & 1) * 8;

    float acc[2][8][4];
#pragma unroll
    for (int i = 0; i < 2; i++)
#pragma unroll
        for (int j = 0; j < 8; j++)
#pragma unroll
            for (int e = 0; e < 4; e++) acc[i][j][e] = 0.0f;

    const int nk = Kseg >> 5;
    const int chBeg = phase * nk;
    const int cnt = phaseSplit ? nk : nk * 3;
    const int ldRow  = tid >> 2, ldC8 = (tid & 3) << 3;
    const int ldRow1 = (tid + 256) >> 2;

    auto issue = [&](int ch, int buf) {
        int ph = (ch >= nk) + (ch >= 2 * nk);
        int within = ch - ph * nk;
        int aOff = (ph == 2) ? Kseg : 0;
        int bOff = (ph == 1) ? Kseg : 0;
        const __nv_bfloat16* Ab = A + (long)m0 * Ka + aOff + (within << 5);
        const __nv_bfloat16* Bb = Bm + (long)n0 * Ka + bOff + (within << 5);
        const uint32_t bo = (uint32_t)buf * BUFB;
        CP_ASYNC16(saB + bo + (uint32_t)((ldRow  * SSTR + ldC8) * 2), Ab + (long)ldRow  * Ka + ldC8);
        CP_ASYNC16(sbB + bo + (uint32_t)((ldRow  * SSTR + ldC8) * 2), Bb + (long)ldRow  * Ka + ldC8);
        CP_ASYNC16(saB + bo + (uint32_t)((ldRow1 * SSTR + ldC8) * 2), Ab + (long)ldRow1 * Ka + ldC8);
        CP_ASYNC16(sbB + bo + (uint32_t)((ldRow1 * SSTR + ldC8) * 2), Bb + (long)ldRow1 * Ka + ldC8);
        CP_COMMIT();
    };

    issue(chBeg, 0);
    issue(chBeg + 1, 1);
    CP_WAIT1();
    __syncthreads();

    for (int i = 0; i < cnt; i++) {
        const int buf = i % 3;
        if (i + 2 < cnt) issue(chBeg + i + 2, (i + 2) % 3);

        const uint32_t sa0 = saB + (uint32_t)buf * BUFB;
        const uint32_t sb0 = sbB + (uint32_t)buf * BUFB;
#pragma unroll
        for (int k16 = 0; k16 < 2; k16++) {
            uint32_t af[2][4];
#pragma unroll
            for (int mi = 0; mi < 2; mi++)
                LDSM_X4(af[mi], sa0 + (uint32_t)((((aRow + mi * 16) * SSTR) + aCol + k16 * 16) * 2));
            uint32_t bf[4][4];
#pragma unroll
            for (int nj = 0; nj < 4; nj++)
                LDSM_X4(bf[nj], sb0 + (uint32_t)((((bRow + nj * 16) * SSTR) + bCol + k16 * 16) * 2));
#pragma unroll
            for (int mi = 0; mi < 2; mi++)
#pragma unroll
                for (int nj = 0; nj < 4; nj++) {
                    mma16816(acc[mi][nj * 2],     af[mi], bf[nj][0], bf[nj][1]);
                    mma16816(acc[mi][nj * 2 + 1], af[mi], bf[nj][2], bf[nj][3]);
                }
        }
        CP_WAIT1();
        __syncthreads();
    }

    // epilogue
#pragma unroll
    for (int mi = 0; mi < 2; mi++) {
#pragma unroll
        for (int nj2 = 0; nj2 < 8; nj2++) {
            int row0 = m0 + wm * 32 + mi * 16 + (lane >> 2);
            int col0 = n0 + wn * 64 + nj2 * 8 + (lane & 3) * 2;
#pragma unroll
            for (int half = 0; half < 2; half++) {
                int gm = row0 + half * 8;
                if (gm < M && col0 + 2 <= N) {
                    float v0 = acc[mi][nj2][half * 2]     * alpha;
                    float v1 = acc[mi][nj2][half * 2 + 1] * alpha;
                    if (biasP) { v0 += biasP[col0]; v1 += biasP[col0 + 1]; }
                    if (act) { v0 = geluf(v0); v1 = geluf(v1); }
                    v0 *= zs; v1 *= zs;
                    if (Cr) { float2 rr; rr.x = v0; rr.y = v1;
                              *(float2*)(Cr + (long)gm * N + col0) = rr; }
                    if (addMode == 1) {
                        v0 += addP[(long)gm * N + col0];
                        v1 += addP[(long)gm * N + col0 + 1];
                    } else if (addMode == 2) {
                        int s = gm % 196;
                        v0 += addP[(long)s * N + col0];
                        v1 += addP[(long)s * N + col0 + 1];
                    }
                    if (Cz) { float2 o; o.x = v0; o.y = v1;
                              *(float2*)(Cz + (long)gm * N + col0) = o; }
                    if (CHz) {
                        __nv_bfloat16 h0 = __float2bfloat16(v0);
                        __nv_bfloat16 h1 = __float2bfloat16(v1);
                        __nv_bfloat16 l0 = __float2bfloat16(v0 - __bfloat162float(h0));
                        __nv_bfloat16 l1 = __float2bfloat16(v1 - __bfloat162float(h1));
                        __nv_bfloat162 hh; hh.x = h0; hh.y = h1;
                        __nv_bfloat162 ll; ll.x = l0; ll.y = l1;
                        *(__nv_bfloat162*)(CHz + (long)gm * 2 * N + col0) = hh;
                        *(__nv_bfloat162*)(CHz + (long)gm * 2 * N + N + col0) = ll;
                    }
                }
            }
        }
    }
}

// ---------------- phase reduce: out = act(p0+p1+p2 + bias)*zs + add ----------------
__global__ void k_redphase(const float* __restrict__ part, float* __restrict__ C,
                           int M, int N, int Z,
                           const int* __restrict__ bIdx, const float* __restrict__ bias,
                           long sBias, const float* __restrict__ zscale, int act,
                           const float* __restrict__ addSrc, long sAdd, int addMode)
{
    long per = (long)M * N;
    long total = (long)Z * per;
    for (long i = blockIdx.x * (long)blockDim.x + threadIdx.x; i < total;
         i += (long)gridDim.x * blockDim.x) {
        int z = (int)(i / per);
        long r = i - (long)z * per;
        int n = (int)(r % N);
        const float* p = part + (long)z * 3 * per + r;
        float v = p[0] + p[per] + p[2 * per];
        if (bias) {
            int bi = bIdx ? bIdx[z] : z;
            v += bias[(long)bi * sBias + n];
        }
        if (act) v = geluf(v);
        if (zscale) v *= zscale[z];
        if (addMode == 1) v += addSrc[(long)z * sAdd + r];
        else if (addMode == 2) {
            int row = (int)(r / N);
            v += addSrc[(long)(row % 196) * N + n];
        }
        C[i] = v;
    }
}

// ---------------- bf16 hi/lo expansion kernels ----------------
__global__ void k_expand8(const float* __restrict__ src, __nv_bfloat16* __restrict__ dst,
                          int Rvalid, int Rpad, int K, int Kseg, long sSrc, int ld, int trans)
{
    long zr = blockIdx.y;
    int r = (int)(zr % Rpad), z = (int)(zr / Rpad);
    int kp0 = (blockIdx.x * blockDim.x + threadIdx.x) << 3;
    if (kp0 >= 2 * Kseg) return;
    bool lo = kp0 >= Kseg;
    int k0 = kp0 - (lo ? Kseg : 0);
    const float* sp = src + (long)z * sSrc;
    __nv_bfloat16 o[8];
#pragma unroll
    for (int j = 0; j < 8; j++) {
        int k = k0 + j;
        float x = 0.0f;
        if (r < Rvalid && k < K)
            x = trans ? sp[(long)k * ld + r] : sp[(long)r * ld + k];
        o[j] = pick_hl(x, lo);
    }
    *(uint4*)(dst + zr * (2L * Kseg) + kp0) = *(uint4*)o;
}

__global__ void k_exp_im2col3(const float* __restrict__ src, __nv_bfloat16* __restrict__ dst,
                              int Cin, int logC, int Kseg, int perBatch)
{
    long row = blockIdx.y;
    int b, s; bool rv = true;
    if (perBatch) { b = (int)(row >> 8); int rp = (int)(row & 255); rv = rp < 196; s = rp; }
    else          { b = (int)(row / 196); s = (int)(row % 196); }
    int kp0 = (blockIdx.x * blockDim.x + threadIdx.x) << 3;
    if (kp0 >= 2 * Kseg) return;
    bool lo = kp0 >= Kseg;
    int k = kp0 - (lo ? Kseg : 0);
    float xv[8];
#pragma unroll
    for (int j = 0; j < 8; j++) xv[j] = 0.0f;
    if (rv) {
        int off = k >> logC, c = k & (Cin - 1);
        int yy = s / 14, xx = s - yy * 14;
        int sy = yy + off / 3 - 1, sx = xx + off % 3 - 1;
        if ((unsigned)sy < 14u && (unsigned)sx < 14u) {
            const float* p = src + (((long)(b * 196 + sy * 14 + sx)) << logC) + c;
            float4 f0 = *(const float4*)p, f1 = *(const float4*)(p + 4);
            xv[0]=f0.x; xv[1]=f0.y; xv[2]=f0.z; xv[3]=f0.w;
            xv[4]=f1.x; xv[5]=f1.y; xv[6]=f1.z; xv[7]=f1.w;
        }
    }
    __nv_bfloat16 o[8];
#pragma unroll
    for (int j = 0; j < 8; j++) o[j] = pick_hl(xv[j], lo);
    *(uint4*)(dst + row * (2L * Kseg) + kp0) = *(uint4*)o;
}

__global__ void k_exp_patch(const float* __restrict__ x, __nv_bfloat16* __restrict__ dst)
{
    int row = blockIdx.y;
    int b = row / 196, s = row % 196;
    int ph = s / 14, pw = s - ph * 14;
    int kp0 = (blockIdx.x * blockDim.x + threadIdx.x) << 3;
    if (kp0 >= 1536) return;
    bool lo = kp0 >= 768;
    int k = kp0 - (lo ? 768 : 0);
    int c = k >> 8, ii = (k >> 4) & 15, jj = k & 15;
    const float* p = x + (((long)(b * 3 + c) * 224) + ph * 16 + ii) * 224 + pw * 16 + jj;
    float4 f0 = *(const float4*)p, f1 = *(const float4*)(p + 4);
    float xv[8] = {f0.x, f0.y, f0.z, f0.w, f1.x, f1.y, f1.z, f1.w};
    __nv_bfloat16 o[8];
#pragma unroll
    for (int j = 0; j < 8; j++) o[j] = pick_hl(xv[j], lo);
    *(uint4*)(dst + (long)row * 1536 + kp0) = *(uint4*)o;
}

__global__ void k_exp_w3x3(const float* __restrict__ src, __nv_bfloat16* __restrict__ dst,
                           int Nout, int Cin, int logC, int Kseg)
{
    int n = blockIdx.y;
    int kp0 = (blockIdx.x * blockDim.x + threadIdx.x) << 3;
    if (kp0 >= 2 * Kseg) return;
    bool lo = kp0 >= Kseg;
    int k = kp0 - (lo ? Kseg : 0);
    int off = k >> logC, c = k & (Cin - 1);
    bool inb = (n < Nout);
    __nv_bfloat16 o[8];
#pragma unroll
    for (int j = 0; j < 8; j++) {
        float xx = inb ? src[((long)n * Cin + c + j) * 9 + off] : 0.0f;
        o[j] = pick_hl(xx, lo);
    }
    *(uint4*)(dst + (long)n * (2L * Kseg) + kp0) = *(uint4*)o;
}

// ---------------- FFMA split-K (skinny M=64) ----------------
__device__ __forceinline__ unsigned long long pk2(float a, float b) {
    unsigned long long r;
    asm("mov.b64 %0, {%1, %2};" : "=l"(r) : "f"(a), "f"(b));
    return r;
}
__device__ __forceinline__ void fma2(unsigned long long& d,
                                     unsigned long long a, unsigned long long b) {
    asm("fma.rn.f32x2 %0, %1, %2, %0;" : "+l"(d) : "l"(a), "l"(b));
}
__device__ __forceinline__ float2 up2(unsigned long long v) {
    float a, b;
    asm("mov.b64 {%0, %1}, %2;" : "=f"(a), "=f"(b) : "l"(v));
    return make_float2(a, b);
}

__global__ __launch_bounds__(256) void k_gemm_split(
    const float* __restrict__ A, const float* __restrict__ Bm, float* __restrict__ C,
    int M, int N, int K, int nsplit)
{
    __shared__ __align__(16) float As[16][68];
    __shared__ __align__(16) float Bs[16][68];
    const int z = blockIdx.z;
    int kc = (K + nsplit - 1) / nsplit;
    int kBeg = z * kc, kEnd = min(K, kBeg + kc);
    C += (long)z * M * N;
    const int tid = threadIdx.x;
    const int m0 = blockIdx.y * 64, n0 = blockIdx.x * 64;
    const int tr = tid >> 4, tc = tid & 15;
    unsigned long long acc[4][2];
#pragma unroll
    for (int i = 0; i < 4; i++) { acc[i][0] = 0ULL; acc[i][1] = 0ULL; }
    for (int k0 = kBeg; k0 < kEnd; k0 += 16) {
#pragma unroll
        for (int i = 0; i < 4; i++) {
            int f = tid + i * 256;
            int m = f >> 4, kk = f & 15;
            int gm = m0 + m, gk = k0 + kk;
            As[kk][m] = (gm < M && gk < kEnd) ? A[(long)gm * K + gk] : 0.0f;
            int gn = n0 + m;
            Bs[kk][m] = (gn < N && gk < kEnd) ? Bm[(long)gn * K + gk] : 0.0f;
        }
        __syncthreads();
#pragma unroll
        for (int kk = 0; kk < 16; kk++) {
            float4 av = *(const float4*)&As[kk][tr * 4];
            ulonglong2 bp = *(const ulonglong2*)&Bs[kk][tc * 4];
            unsigned long long a0 = pk2(av.x, av.x), a1 = pk2(av.y, av.y);
            unsigned long long a2 = pk2(av.z, av.z), a3 = pk2(av.w, av.w);
            fma2(acc[0][0], a0, bp.x); fma2(acc[0][1], a0, bp.y);
            fma2(acc[1][0], a1, bp.x); fma2(acc[1][1], a1, bp.y);
            fma2(acc[2][0], a2, bp.x); fma2(acc[2][1], a2, bp.y);
            fma2(acc[3][0], a3, bp.x); fma2(acc[3][1], a3, bp.y);
        }
        __syncthreads();
    }
#pragma unroll
    for (int i = 0; i < 4; i++) {
        int gm = m0 + tr * 4 + i;
        if (gm >= M) continue;
#pragma unroll
        for (int jp = 0; jp < 2; jp++) {
            float2 v = up2(acc[i][jp]);
            int gn = n0 + tc * 4 + jp * 2;
            if (gn < N)     C[(long)gm * N + gn] = v.x;
            if (gn + 1 < N) C[(long)gm * N + gn + 1] = v.y;
        }
    }
}

// ---------------- small kernels ----------------
__global__ void k_softmax(float* __restrict__ sc) {
    long row = blockIdx.x;
    float* p = sc + row * 196;
    int t = threadIdx.x;
    __shared__ float red[256];
    float v = (t < 196) ? p[t] : -3.4e38f;
    red[t] = v; __syncthreads();
    for (int s = 128; s > 0; s >>= 1) { if (t < s) red[t] = fmaxf(red[t], red[t + s]); __syncthreads(); }
    float mx = red[0]; __syncthreads();
    float ex = (t < 196) ? expf(v - mx) : 0.0f;
    red[t] = ex; __syncthreads();
    for (int s = 128; s > 0; s >>= 1) { if (t < s) red[t] += red[t + s]; __syncthreads(); }
    float inv = 1.0f / red[0];
    if (t < 196) p[t] = ex * inv;
}
__global__ void k_bnstat(const float* __restrict__ x, float* __restrict__ psum,
                         float* __restrict__ psq) {
    int c = threadIdx.x, ch = blockIdx.x;
    float s = 0.0f, q = 0.0f;
    long r0 = (long)ch * 196;
    for (int r = 0; r < 196; r++) {
        float v = x[(r0 + r) * 256 + c];
        s += v; q += v * v;
    }
    psum[ch * 256 + c] = s; psq[ch * 256 + c] = q;
}
__global__ void k_bnfin(const float* __restrict__ psum, const float* __restrict__ psq,
                        float* __restrict__ mean, float* __restrict__ istd) {
    int c = threadIdx.x;
    float s = 0.0f, q = 0.0f;
    for (int i = 0; i < 64; i++) { s += psum[i * 256 + c]; q += psq[i * 256 + c]; }
    float m = s / 12544.0f;
    float var = q / 12544.0f - m * m;
    mean[c] = m; istd[c] = rsqrtf(var + 1e-5f);
}
__global__ void k_bnnorm(const float* __restrict__ x, float* __restrict__ out,
                         const float* __restrict__ mean, const float* __restrict__ istd,
                         const float* __restrict__ g, const float* __restrict__ b,
                         int transposed, __nv_bfloat16* __restrict__ hl) {
    long total = ROWS * 256;
    for (long i = blockIdx.x * (long)blockDim.x + threadIdx.x; i < total;
         i += (long)gridDim.x * blockDim.x) {
        int c = (int)(i & 255);
        long row = i >> 8;
        float v = (x[i] - mean[c]) * istd[c] * g[c] + b[c];
        if (!transposed) out[i] = v;
        else {
            int bb = (int)(row / 196), ss = (int)(row % 196);
            out[(long)bb * 50176 + c * 196 + ss] = v;
        }
        if (hl) {
            __nv_bfloat16 hi = __float2bfloat16(v);
            hl[row * 512 + c] = hi;
            hl[row * 512 + 256 + c] = __float2bfloat16(v - __bfloat162float(hi));
        }
    }
}
__global__ void k_tr32(const float* __restrict__ src, float* __restrict__ dst) {
    long total = ROWS * 32;
    for (long i = blockIdx.x * (long)blockDim.x + threadIdx.x; i < total;
         i += (long)gridDim.x * blockDim.x) {
        int b = (int)(i / 6272), r = (int)(i % 6272);
        int c = r / 196, s = r % 196;
        dst[i] = src[((long)(b * 196 + s)) * 32 + c];
    }
}
__global__ void k_reduce(const float* __restrict__ part, float* __restrict__ out,
                         int M, int N, int nsplit, const float* __restrict__ bias, int act) {
    long total = (long)M * N;
    for (long i = blockIdx.x * (long)blockDim.x + threadIdx.x; i < total;
         i += (long)gridDim.x * blockDim.x) {
        int n = (int)(i % N);
        float s = 0.0f;
        for (int p = 0; p < nsplit; p++) s += part[(long)p * total + i];
        if (bias) s += bias[n];
        if (act) s = geluf(s);
        out[i] = s;
    }
}
__global__ void k_rd2(const float* __restrict__ rfc, const float* __restrict__ w,
                      const float* __restrict__ b, int* __restrict__ pos,
                      float* __restrict__ scale) {
    int bb = blockIdx.x, t = threadIdx.x;
    int e = t >> 5, lane = t & 31;
    const float* xr = rfc + (long)bb * 3136;
    const float* wr = w + (long)e * 3136;
    float s = 0.0f;
    for (int k = lane; k < 3136; k += 32) s += xr[k] * wr[k];
    for (int o = 16; o > 0; o >>= 1) s += __shfl_down_sync(0xffffffffu, s, o);
    __shared__ float lg[8];
    if (lane == 0) lg[e] = s + b[e];
    __syncthreads();
    if (t == 0) {
        int best = 0; float bv = lg[0];
        for (int e2 = 1; e2 < 8; e2++) if (lg[e2] > bv) { bv = lg[e2]; best = e2; }
        pos[bb] = best; scale[bb] = bv;
    }
}

// ---------------- host ----------------
static inline int GS(long n) { return (int)((n + 255) / 256); }

static void tgemm(const __nv_bfloat16* A, const __nv_bfloat16* B,
                  float* C, float* Craw, __nv_bfloat16* CHL,
                  int M, int Mpad, int N, int Npad, int Kseg, int Z,
                  long sA, long sB, long sC, long sCHL,
                  const int* bIdx, const float* bias, long sBias,
                  const float* zscale, float alpha, int act,
                  const float* addSrc, long sAdd, int addMode) {
    cudaFuncSetAttribute(k_tgemm, cudaFuncAttributeMaxDynamicSharedMemorySize, SMEM_T);
    dim3 g(Npad / 128, Mpad / 128, Z);
    k_tgemm<<<g, 256, SMEM_T>>>(A, B, C, Craw, CHL, M, N, Kseg, sA, sB, sC, sCHL,
                                bIdx, bias, sBias, zscale, alpha, act, addSrc, sAdd, addMode, 0);
}
// phase-split GEMM: partials [z][phase][M*N]
static void tgemmP(const __nv_bfloat16* A, const __nv_bfloat16* B, float* part,
                   int M, int Mpad, int N, int Npad, int Kseg, int Z,
                   long sA, long sB, const int* bIdx) {
    cudaFuncSetAttribute(k_tgemm, cudaFuncAttributeMaxDynamicSharedMemorySize, SMEM_T);
    dim3 g(Npad / 128, Mpad / 128, 3 * Z);
    k_tgemm<<<g, 256, SMEM_T>>>(A, B, part, nullptr, nullptr, M, N, Kseg,
                                sA, sB, (long)M * N, 0, bIdx, nullptr, 0,
                                nullptr, 1.0f, 0, nullptr, 0, 0, 1);
}
static void redphase(const float* part, float* C, int M, int N, int Z,
                     const int* bIdx, const float* bias, long sBias,
                     const float* zscale, int act,
                     const float* addSrc, long sAdd, int addMode) {
    k_redphase<<<GS((long)Z * M * N), 256>>>(part, C, M, N, Z, bIdx, bias, sBias,
                                             zscale, act, addSrc, sAdd, addMode);
}
static void expand8(const float* src, __nv_bfloat16* dst, int Rvalid, int Rpad,
                    int K, int Kseg, long sSrc, int ld, int trans, int Z) {
    dim3 g((2 * Kseg / 8 + 127) / 128, Z * Rpad);
    k_expand8<<<g, 128>>>(src, dst, Rvalid, Rpad, K, Kseg, sSrc, ld, trans);
}
static void exp_im2col3(const float* src, __nv_bfloat16* dst, int Cin, int logC,
                        int Kseg, int perBatch) {
    dim3 g((2 * Kseg / 8 + 127) / 128, perBatch ? 16384 : 12544);
    k_exp_im2col3<<<g, 128>>>(src, dst, Cin, logC, Kseg, perBatch);
}

extern "C" void kernel_launch(void* const* d_in, const int* in_sizes, int n_in,
                              void* d_out, int out_size) {
    const float* x       = (const float*)d_in[0];
    const float* patch_w = (const float*)d_in[1];
    const float* patch_b = (const float*)d_in[2];
    const float* pos_emb = (const float*)d_in[3];
    const float* wo_w    = (const float*)d_in[4];
    const float* wo_b    = (const float*)d_in[5];
    const float* bn1_g   = (const float*)d_in[6];
    const float* bn1_b   = (const float*)d_in[7];
    const float* rc1_w   = (const float*)d_in[8];
    const float* rc1_b   = (const float*)d_in[9];
    const float* rc2_w   = (const float*)d_in[10];
    const float* rc2_b   = (const float*)d_in[11];
    const float* rc3_w   = (const float*)d_in[12];
    const float* rc3_b   = (const float*)d_in[13];
    const float* rd1_w   = (const float*)d_in[14];
    const float* rd1_b   = (const float*)d_in[15];
    const float* rd2_w   = (const float*)d_in[16];
    const float* rd2_b   = (const float*)d_in[17];
    const float* exp_w1  = (const float*)d_in[18];
    const float* exp_b1  = (const float*)d_in[19];
    const float* exp_w2  = (const float*)d_in[20];
    const float* exp_b2  = (const float*)d_in[21];
    const float* shard_w = (const float*)d_in[22];
    const float* shard_b = (const float*)d_in[23];
    const float* bn2_g   = (const float*)d_in[24];
    const float* bn2_b   = (const float*)d_in[25];
    const float* od1_w   = (const float*)d_in[26];
    const float* od1_b   = (const float*)d_in[27];
    const float* od2_w   = (const float*)d_in[28];
    const float* od2_b   = (const float*)d_in[29];

    float* F = nullptr;            cudaGetSymbolAddress((void**)&F, g_f);
    __nv_bfloat16* Hh = nullptr;   cudaGetSymbolAddress((void**)&Hh, g_h);
    int* posP = nullptr;           cudaGetSymbolAddress((void**)&posP, g_pos);

    float *Y = F + O_Y, *sc = F + O_SC, *re2 = F + O_RE2;
    float *pre1 = F + O_PRE1, *outb = F + O_OUT, *r1 = F + O_R1, *r2 = F + O_R2;
    float *r3 = F + O_R3, *r3t = F + O_R3T, *part = F + O_PART, *rfc = F + O_RFC;
    float *h1 = F + O_H1, *rexp = F + O_REX, *out1 = F + O_OUT1, *ot = F + O_OT;
    float *ofc = F + O_OFC, *bs1 = F + O_BS1, *bs2 = F + O_BS2;
    float *meanp = F + O_MEAN, *istdp = F + O_ISTD, *scalp = F + O_SCAL;

    __nv_bfloat16 *ABig = Hh + B_ABIG, *YAB = Hh + B_YAB, *ATT = Hh + B_ATT;
    __nv_bfloat16 *YT = Hh + B_YT, *REAHL = Hh + B_REAHL, *OUTHL = Hh + B_OUTHL;
    __nv_bfloat16 *PW = Hh + B_PW, *WO = Hh + B_WO, *SH = Hh + B_SH;
    __nv_bfloat16 *RC1 = Hh + B_RC1, *RC2 = Hh + B_RC2, *RC3 = Hh + B_RC3;
    __nv_bfloat16 *EW1 = Hh + B_EW1, *EW2 = Hh + B_EW2;

    const float inv14 = 1.0f / sqrtf(14.0f);

    // launch order: idx 3 = patch GEMM (split, profiled)
    expand8(patch_w, PW, 256, 256, 768, 768, 0, 768, 0, 1);            // 0
    { dim3 g(2, 12544); k_exp_patch<<<g, 128>>>(x, ABig); }            // 1
    expand8(wo_w, WO, 256, 256, 256, 256, 0, 256, 0, 1);               // 2
    tgemmP(ABig, PW, part, 12544, 12544, 256, 256, 768, 1, 0, 0, nullptr);  // 3
    redphase(part, Y, 12544, 256, 1, nullptr, patch_b, 0, nullptr, 0, pos_emb, 0, 2);

    expand8(shard_w, SH, 256, 256, 256, 256, 0, 256, 0, 1);
    { dim3 g(5, 128);  k_exp_w3x3<<<g, 128>>>(rc1_w, RC1, 128, 256, 8, 2304); }
    { dim3 g(3, 128);  k_exp_w3x3<<<g, 128>>>(rc2_w, RC2, 64, 128, 7, 1152); }
    { dim3 g(2, 128);  k_exp_w3x3<<<g, 128>>>(rc3_w, RC3, 32, 64, 6, 576); }
    { dim3 g(5, 2048); k_exp_w3x3<<<g, 128>>>(exp_w1, EW1, 2048, 256, 8, 2304); }
    { dim3 g(5, 2048); k_exp_w3x3<<<g, 128>>>(exp_w2, EW2, 2048, 256, 8, 2304); }

    // attention (fused epilogues; K too small for phase-split to pay)
    expand8(Y, YAB, 196, 256, 256, 256, 196 * 256, 256, 0, 64);
    tgemm(YAB, YAB, sc, nullptr, nullptr, 196, 256, 196, 256, 256, 64,
          256L * 512, 256L * 512, 196L * 196, 0, nullptr, nullptr, 0, nullptr, inv14, 0,
          nullptr, 0, 0);
    k_softmax<<<12544, 256>>>(sc);
    expand8(sc, ATT, 196, 256, 196, 256, 196 * 196, 196, 0, 64);
    expand8(Y, YT, 256, 256, 196, 256, 196 * 256, 256, 1, 64);
    tgemm(ATT, YT, nullptr, nullptr, REAHL, 196, 256, 256, 256, 256, 64,
          256L * 512, 256L * 512, 0, 196L * 512, nullptr, nullptr, 0, nullptr, 1.0f, 0,
          nullptr, 0, 0);
    tgemm(REAHL, WO, pre1, re2, nullptr, 12544, 12544, 256, 256, 256, 1,
          0, 0, 0, 0, nullptr, wo_b, 0, nullptr, 1.0f, 0, Y, 0, 1);

    // bn1 (hi/lo side-output feeds shard GEMM)
    k_bnstat<<<64, 256>>>(pre1, bs1, bs2);
    k_bnfin<<<1, 256>>>(bs1, bs2, meanp, istdp);
    k_bnnorm<<<GS(ROWS * 256), 256>>>(pre1, outb, meanp, istdp, bn1_g, bn1_b, 0, OUTHL);

    // shard shortcut (fused)
    tgemm(OUTHL, SH, out1, nullptr, nullptr, 12544, 12544, 256, 256, 256, 1,
          0, 0, 0, 0, nullptr, shard_b, 0, nullptr, 1.0f, 0, nullptr, 0, 0);

    // router convs (phase-split)
    exp_im2col3(outb, ABig, 256, 8, 2304, 0);
    tgemmP(ABig, RC1, part, 12544, 12544, 128, 128, 2304, 1, 0, 0, nullptr);
    redphase(part, r1, 12544, 128, 1, nullptr, rc1_b, 0, nullptr, 1, nullptr, 0, 0);
    exp_im2col3(r1, ABig, 128, 7, 1152, 0);
    tgemmP(ABig, RC2, part, 12544, 12544, 64, 128, 1152, 1, 0, 0, nullptr);
    redphase(part, r2, 12544, 64, 1, nullptr, rc2_b, 0, nullptr, 1, nullptr, 0, 0);
    exp_im2col3(r2, ABig, 64, 6, 576, 0);
    tgemmP(ABig, RC3, part, 12544, 12544, 32, 128, 576, 1, 0, 0, nullptr);
    redphase(part, r3, 12544, 32, 1, nullptr, rc3_b, 0, nullptr, 1, nullptr, 0, 0);
    k_tr32<<<GS(ROWS * 32), 256>>>(r3, r3t);

    // router dense (FFMA split-K) + argmax gate
    { dim3 g(49, 1, 8); k_gemm_split<<<g, 256>>>(r3t, rd1_w, part, 64, 3136, 6272, 8); }
    k_reduce<<<GS(64L * 3136), 256>>>(part, rfc, 64, 3136, 8, rd1_b, 1);
    k_rd2<<<64, 256>>>(rfc, rd2_w, rd2_b, posP, scalp);

    // experts (phase-split; reduce applies bias+gelu[, gate+out1])
    exp_im2col3(re2, ABig, 256, 8, 2304, 1);
    tgemmP(ABig, EW1, part, 196, 256, 256, 256, 2304, 64,
           256L * 4608, 256L * 4608, posP);
    redphase(part, h1, 196, 256, 64, posP, exp_b1, 256, nullptr, 1, nullptr, 0, 0);
    exp_im2col3(h1, ABig, 256, 8, 2304, 1);
    tgemmP(ABig, EW2, part, 196, 256, 256, 256, 2304, 64,
           256L * 4608, 256L * 4608, posP);
    redphase(part, rexp, 196, 256, 64, posP, exp_b2, 256, scalp, 1,
             out1, 196L * 256, 1);

    // bn2 (transposed write [b][c][s])
    k_bnstat<<<64, 256>>>(rexp, bs1, bs2);
    k_bnfin<<<1, 256>>>(bs1, bs2, meanp, istdp);
    k_bnnorm<<<GS(ROWS * 256), 256>>>(rexp, ot, meanp, istdp, bn2_g, bn2_b, 1, nullptr);

    // output head (FFMA split-K)
    { dim3 g(16, 1, 32); k_gemm_split<<<g, 256>>>(ot, od1_w, part, 64, 1024, 50176, 32); }
    k_reduce<<<GS(64L * 1024), 256>>>(part, ofc, 64, 1024, 32, od1_b, 1);
    { dim3 g(16, 1, 8); k_gemm_split<<<g, 256>>>(ofc, od2_w, part, 64, 1000, 1024, 8); }
    k_reduce<<<GS(64L * 1000), 256>>>(part, (float*)d_out, 64, 1000, 8, od2_b, 0);
}

// round 15
// speedup vs baseline: 1.0707x; 1.0707x over previous
#include <cuda_runtime.h>
#include <cuda_bf16.h>
#include <math.h>
#include <stdint.h>

constexpr int  NB   = 64;
constexpr long ROWS = 12544;

// ---------------- fp32 scratch ----------------
constexpr long O_Y=0, O_SC=O_Y+3211264, O_RE2=O_SC+2458624,
 O_PRE1=O_RE2+3211264, O_OUT=O_PRE1+3211264, O_R1=O_OUT+3211264, O_R2=O_R1+1605632,
 O_R3=O_R2+802816, O_R3T=O_R3+401408, O_PART=O_R3T+401408,
 O_RFC=O_PART+9633792,
 O_H1=O_RFC+200704, O_REX=O_H1+3211264, O_OUT1=O_REX+3211264, O_OT=O_OUT1+3211264,
 O_OFC=O_OT+3211264, O_BS1=O_OFC+65536, O_BS2=O_BS1+16384, O_MEAN=O_BS2+16384,
 O_ISTD=O_MEAN+256, O_SCAL=O_ISTD+256, O_FEND=O_SCAL+64;
__device__ float g_f[O_FEND];
__device__ int   g_pos[64];

// ---------------- bf16 scratch ([hi|lo] 2-segment layouts) ----------------
constexpr long B_ABIG=0;                                    // 16384 x 4608
constexpr long B_YAB  = B_ABIG + 75497472L;                 // 64 x 256 x 512
constexpr long B_ATT  = B_YAB  + 8388608L;
constexpr long B_YT   = B_ATT  + 8388608L;
constexpr long B_REAHL= B_YT   + 8388608L;                  // 12544 x 512
constexpr long B_OUTHL= B_REAHL+ 6422528L;                  // 12544 x 512
constexpr long B_PW   = B_OUTHL+ 6422528L;                  // 256 x 1536
constexpr long B_WO   = B_PW   + 393216L;
constexpr long B_SH   = B_WO   + 131072L;
constexpr long B_RC1  = B_SH   + 131072L;                   // 128 x 4608
constexpr long B_RC2  = B_RC1  + 589824L;
constexpr long B_RC3  = B_RC2  + 294912L;
constexpr long B_EW1  = B_RC3  + 147456L;                   // 2048 x 4608
constexpr long B_EW2  = B_EW1  + 9437184L;
constexpr long B_HEND = B_EW2  + 9437184L;
__device__ __align__(1024) __nv_bfloat16 g_h[B_HEND];

// ---------------- helpers ----------------
__device__ __forceinline__ uint32_t smem_u32(const void* p) {
    uint32_t a;
    asm("{ .reg .u64 t; cvta.to.shared.u64 t, %1; cvt.u32.u64 %0, t; }" : "=r"(a) : "l"(p));
    return a;
}
__device__ __forceinline__ float geluf(float v) {
    return 0.5f * v * (1.0f + erff(v * 0.70710678118654752440f));
}
#define CP_ASYNC16(dst, src) \
    asm volatile("cp.async.ca.shared.global [%0], [%1], 16;" :: "r"(dst), "l"(src))
#define CP_COMMIT() asm volatile("cp.async.commit_group;" ::: "memory")
#define CP_WAIT1()  asm volatile("cp.async.wait_group 1;" ::: "memory")
#define LDSM_X4(r, addr) \
    asm volatile("ldmatrix.sync.aligned.m8n8.x4.shared.b16 {%0,%1,%2,%3}, [%4];" \
        : "=r"((r)[0]), "=r"((r)[1]), "=r"((r)[2]), "=r"((r)[3]) : "r"(addr))
__device__ __forceinline__ void mma16816(float* c, const uint32_t* a, uint32_t b0, uint32_t b1) {
    asm volatile("mma.sync.aligned.m16n8k16.row.col.f32.bf16.bf16.f32 "
        "{%0,%1,%2,%3}, {%4,%5,%6,%7}, {%8,%9}, {%0,%1,%2,%3};"
        : "+f"(c[0]), "+f"(c[1]), "+f"(c[2]), "+f"(c[3])
        : "r"(a[0]), "r"(a[1]), "r"(a[2]), "r"(a[3]), "r"(b0), "r"(b1));
}
__device__ __forceinline__ __nv_bfloat16 pick_hl(float x, bool lo) {
    __nv_bfloat16 hi = __float2bfloat16(x);
    return lo ? __float2bfloat16(x - __bfloat162float(hi)) : hi;
}

constexpr int SSTR = 40;
constexpr uint32_t BUFB = 128 * SSTR * 2;      // 10240 B
constexpr int SMEM_T = 6 * (int)BUFB;          // 61440

// ---------------- LEAN split GEMM: one phase per CTA, raw partial store ----------------
__global__ __launch_bounds__(256) void k_tgemmP(
    const __nv_bfloat16* __restrict__ A, const __nv_bfloat16* __restrict__ Bm,
    float* __restrict__ C, int M, int N, int Kseg,
    long sA, long sB, long sC,
    const int* __restrict__ bIdx)
{
    extern __shared__ __align__(16) char smem[];
    const int tid = threadIdx.x, w = tid >> 5, lane = tid & 31;
    const int zt = blockIdx.z, m0 = blockIdx.y * 128, n0 = blockIdx.x * 128;
    const int zb = zt / 3, phase = zt - zb * 3;
    const int Ka = 2 * Kseg;

    A += (long)zb * sA;
    const int bi = bIdx ? bIdx[zb] : zb;
    Bm += (long)bi * sB;
    float* Cz = C + (long)zt * sC;

    const uint32_t saB = smem_u32(smem);
    const uint32_t sbB = saB + 3 * BUFB;

    const int wm = w & 3, wn = w >> 2;
    const int matId = lane >> 3;
    const int aRow = wm * 32 + (matId & 1) * 8 + (lane & 7);
    const int aCol = (matId >> 1) * 8;
    const int bRow = wn * 64 + (matId >> 1) * 8 + (lane & 7);
    const int bCol = (matId & 1) * 8;

    float acc[2][8][4];
#pragma unroll
    for (int i = 0; i < 2; i++)
#pragma unroll
        for (int j = 0; j < 8; j++)
#pragma unroll
            for (int e = 0; e < 4; e++) acc[i][j][e] = 0.0f;

    const int nk = Kseg >> 5;
    const int aOffP = (phase == 2) ? Kseg : 0;
    const int bOffP = (phase == 1) ? Kseg : 0;
    const int ldRow  = tid >> 2, ldC8 = (tid & 3) << 3;
    const int ldRow1 = (tid + 256) >> 2;

    auto issue = [&](int within, int buf) {
        const __nv_bfloat16* Ab = A + (long)m0 * Ka + aOffP + (within << 5);
        const __nv_bfloat16* Bb = Bm + (long)n0 * Ka + bOffP + (within << 5);
        const uint32_t bo = (uint32_t)buf * BUFB;
        CP_ASYNC16(saB + bo + (uint32_t)((ldRow  * SSTR + ldC8) * 2), Ab + (long)ldRow  * Ka + ldC8);
        CP_ASYNC16(sbB + bo + (uint32_t)((ldRow  * SSTR + ldC8) * 2), Bb + (long)ldRow  * Ka + ldC8);
        CP_ASYNC16(saB + bo + (uint32_t)((ldRow1 * SSTR + ldC8) * 2), Ab + (long)ldRow1 * Ka + ldC8);
        CP_ASYNC16(sbB + bo + (uint32_t)((ldRow1 * SSTR + ldC8) * 2), Bb + (long)ldRow1 * Ka + ldC8);
        CP_COMMIT();
    };

    issue(0, 0);
    issue(1, 1);
    CP_WAIT1();
    __syncthreads();

    for (int i = 0; i < nk; i++) {
        const int buf = i % 3;
        if (i + 2 < nk) issue(i + 2, (i + 2) % 3);

        const uint32_t sa0 = saB + (uint32_t)buf * BUFB;
        const uint32_t sb0 = sbB + (uint32_t)buf * BUFB;
#pragma unroll
        for (int k16 = 0; k16 < 2; k16++) {
            uint32_t af[2][4];
#pragma unroll
            for (int mi = 0; mi < 2; mi++)
                LDSM_X4(af[mi], sa0 + (uint32_t)((((aRow + mi * 16) * SSTR) + aCol + k16 * 16) * 2));
            uint32_t bf[4][4];
#pragma unroll
            for (int nj = 0; nj < 4; nj++)
                LDSM_X4(bf[nj], sb0 + (uint32_t)((((bRow + nj * 16) * SSTR) + bCol + k16 * 16) * 2));
#pragma unroll
            for (int mi = 0; mi < 2; mi++)
#pragma unroll
                for (int nj = 0; nj < 4; nj++) {
                    mma16816(acc[mi][nj * 2],     af[mi], bf[nj][0], bf[nj][1]);
                    mma16816(acc[mi][nj * 2 + 1], af[mi], bf[nj][2], bf[nj][3]);
                }
        }
        CP_WAIT1();
        __syncthreads();
    }

#pragma unroll
    for (int mi = 0; mi < 2; mi++) {
#pragma unroll
        for (int nj2 = 0; nj2 < 8; nj2++) {
            int row0 = m0 + wm * 32 + mi * 16 + (lane >> 2);
            int col0 = n0 + wn * 64 + nj2 * 8 + (lane & 3) * 2;
#pragma unroll
            for (int half = 0; half < 2; half++) {
                int gm = row0 + half * 8;
                if (gm < M && col0 + 2 <= N) {
                    float2 o;
                    o.x = acc[mi][nj2][half * 2];
                    o.y = acc[mi][nj2][half * 2 + 1];
                    *(float2*)(Cz + (long)gm * N + col0) = o;
                }
            }
        }
    }
}

// ---------------- FUSED GEMM: 3 phases accumulated, full epilogue ----------------
__global__ __launch_bounds__(256) void k_tgemmF(
    const __nv_bfloat16* __restrict__ A, const __nv_bfloat16* __restrict__ Bm,
    float* __restrict__ C, float* __restrict__ Craw, __nv_bfloat16* __restrict__ CHL,
    int M, int N, int Kseg,
    long sA, long sB, long sC, long sCHL,
    const float* __restrict__ bias,
    float alpha, int act,
    const float* __restrict__ addSrc, long sAdd, int addMode)
{
    extern __shared__ __align__(16) char smem[];
    const int tid = threadIdx.x, w = tid >> 5, lane = tid & 31;
    const int z = blockIdx.z, m0 = blockIdx.y * 128, n0 = blockIdx.x * 128;
    const int Ka = 2 * Kseg;

    A += (long)z * sA;
    Bm += (long)z * sB;
    float* Cz  = C    ? C    + (long)z * sC  : nullptr;
    float* Cr  = Craw ? Craw + (long)z * sC  : nullptr;
    __nv_bfloat16* CHz = CHL ? CHL + (long)z * sCHL : nullptr;
    const float* addP = addSrc ? addSrc + (long)z * sAdd : nullptr;

    const uint32_t saB = smem_u32(smem);
    const uint32_t sbB = saB + 3 * BUFB;

    const int wm = w & 3, wn = w >> 2;
    const int matId = lane >> 3;
    const int aRow = wm * 32 + (matId & 1) * 8 + (lane & 7);
    const int aCol = (matId >> 1) * 8;
    const int bRow = wn * 64 + (matId >> 1) * 8 + (lane & 7);
    const int bCol = (matId & 1) * 8;

    float acc[2][8][4];
#pragma unroll
    for (int i = 0; i < 2; i++)
#pragma unroll
        for (int j = 0; j < 8; j++)
#pragma unroll
            for (int e = 0; e < 4; e++) acc[i][j][e] = 0.0f;

    const int nk = Kseg >> 5;
    const int ntot = nk * 3;
    const int ldRow  = tid >> 2, ldC8 = (tid & 3) << 3;
    const int ldRow1 = (tid + 256) >> 2;

    auto issue = [&](int ch, int buf) {
        int ph = (ch >= nk) + (ch >= 2 * nk);
        int within = ch - ph * nk;
        int aOff = (ph == 2) ? Kseg : 0;
        int bOff = (ph == 1) ? Kseg : 0;
        const __nv_bfloat16* Ab = A + (long)m0 * Ka + aOff + (within << 5);
        const __nv_bfloat16* Bb = Bm + (long)n0 * Ka + bOff + (within << 5);
        const uint32_t bo = (uint32_t)buf * BUFB;
        CP_ASYNC16(saB + bo + (uint32_t)((ldRow  * SSTR + ldC8) * 2), Ab + (long)ldRow  * Ka + ldC8);
        CP_ASYNC16(sbB + bo + (uint32_t)((ldRow  * SSTR + ldC8) * 2), Bb + (long)ldRow  * Ka + ldC8);
        CP_ASYNC16(saB + bo + (uint32_t)((ldRow1 * SSTR + ldC8) * 2), Ab + (long)ldRow1 * Ka + ldC8);
        CP_ASYNC16(sbB + bo + (uint32_t)((ldRow1 * SSTR + ldC8) * 2), Bb + (long)ldRow1 * Ka + ldC8);
        CP_COMMIT();
    };

    issue(0, 0);
    issue(1, 1);
    CP_WAIT1();
    __syncthreads();

    for (int i = 0; i < ntot; i++) {
        const int buf = i % 3;
        if (i + 2 < ntot) issue(i + 2, (i + 2) % 3);

        const uint32_t sa0 = saB + (uint32_t)buf * BUFB;
        const uint32_t sb0 = sbB + (uint32_t)buf * BUFB;
#pragma unroll
        for (int k16 = 0; k16 < 2; k16++) {
            uint32_t af[2][4];
#pragma unroll
            for (int mi = 0; mi < 2; mi++)
                LDSM_X4(af[mi], sa0 + (uint32_t)((((aRow + mi * 16) * SSTR) + aCol + k16 * 16) * 2));
            uint32_t bf[4][4];
#pragma unroll
            for (int nj = 0; nj < 4; nj++)
                LDSM_X4(bf[nj], sb0 + (uint32_t)((((bRow + nj * 16) * SSTR) + bCol + k16 * 16) * 2));
#pragma unroll
            for (int mi = 0; mi < 2; mi++)
#pragma unroll
                for (int nj = 0; nj < 4; nj++) {
                    mma16816(acc[mi][nj * 2],     af[mi], bf[nj][0], bf[nj][1]);
                    mma16816(acc[mi][nj * 2 + 1], af[mi], bf[nj][2], bf[nj][3]);
                }
        }
        CP_WAIT1();
        __syncthreads();
    }

#pragma unroll
    for (int mi = 0; mi < 2; mi++) {
#pragma unroll
        for (int nj2 = 0; nj2 < 8; nj2++) {
            int row0 = m0 + wm * 32 + mi * 16 + (lane >> 2);
            int col0 = n0 + wn * 64 + nj2 * 8 + (lane & 3) * 2;
#pragma unroll
            for (int half = 0; half < 2; half++) {
                int gm = row0 + half * 8;
                if (gm < M && col0 + 2 <= N) {
                    float v0 = acc[mi][nj2][half * 2]     * alpha;
                    float v1 = acc[mi][nj2][half * 2 + 1] * alpha;
                    if (bias) { v0 += bias[col0]; v1 += bias[col0 + 1]; }
                    if (act) { v0 = geluf(v0); v1 = geluf(v1); }
                    if (Cr) { float2 rr; rr.x = v0; rr.y = v1;
                              *(float2*)(Cr + (long)gm * N + col0) = rr; }
                    if (addMode == 1) {
                        v0 += addP[(long)gm * N + col0];
                        v1 += addP[(long)gm * N + col0 + 1];
                    }
                    if (Cz) { float2 o; o.x = v0; o.y = v1;
                              *(float2*)(Cz + (long)gm * N + col0) = o; }
                    if (CHz) {
                        __nv_bfloat16 h0 = __float2bfloat16(v0);
                        __nv_bfloat16 h1 = __float2bfloat16(v1);
                        __nv_bfloat16 l0 = __float2bfloat16(v0 - __bfloat162float(h0));
                        __nv_bfloat16 l1 = __float2bfloat16(v1 - __bfloat162float(h1));
                        __nv_bfloat162 hh; hh.x = h0; hh.y = h1;
                        __nv_bfloat162 ll; ll.x = l0; ll.y = l1;
                        *(__nv_bfloat162*)(CHz + (long)gm * 2 * N + col0) = hh;
                        *(__nv_bfloat162*)(CHz + (long)gm * 2 * N + N + col0) = ll;
                    }
                }
            }
        }
    }
}

// ---------------- phase reduce: out = act(p0+p1+p2 + bias)*zs + add ----------------
__global__ void k_redphase(const float* __restrict__ part, float* __restrict__ C,
                           int M, int N, int Z,
                           const int* __restrict__ bIdx, const float* __restrict__ bias,
                           long sBias, const float* __restrict__ zscale, int act,
                           const float* __restrict__ addSrc, long sAdd, int addMode)
{
    long per = (long)M * N;
    long total = (long)Z * per;
    for (long i = blockIdx.x * (long)blockDim.x + threadIdx.x; i < total;
         i += (long)gridDim.x * blockDim.x) {
        int z = (int)(i / per);
        long r = i - (long)z * per;
        int n = (int)(r % N);
        const float* p = part + (long)z * 3 * per + r;
        float v = p[0] + p[per] + p[2 * per];
        if (bias) {
            int bi = bIdx ? bIdx[z] : z;
            v += bias[(long)bi * sBias + n];
        }
        if (act) v = geluf(v);
        if (zscale) v *= zscale[z];
        if (addMode == 1) v += addSrc[(long)z * sAdd + r];
        else if (addMode == 2) {
            int row = (int)(r / N);
            v += addSrc[(long)(row % 196) * N + n];
        }
        C[i] = v;
    }
}

// ---------------- bf16 hi/lo expansion kernels ----------------
__global__ void k_expand8(const float* __restrict__ src, __nv_bfloat16* __restrict__ dst,
                          int Rvalid, int Rpad, int K, int Kseg, long sSrc, int ld, int trans)
{
    long zr = blockIdx.y;
    int r = (int)(zr % Rpad), z = (int)(zr / Rpad);
    int kp0 = (blockIdx.x * blockDim.x + threadIdx.x) << 3;
    if (kp0 >= 2 * Kseg) return;
    bool lo = kp0 >= Kseg;
    int k0 = kp0 - (lo ? Kseg : 0);
    const float* sp = src + (long)z * sSrc;
    __nv_bfloat16 o[8];
#pragma unroll
    for (int j = 0; j < 8; j++) {
        int k = k0 + j;
        float x = 0.0f;
        if (r < Rvalid && k < K)
            x = trans ? sp[(long)k * ld + r] : sp[(long)r * ld + k];
        o[j] = pick_hl(x, lo);
    }
    *(uint4*)(dst + zr * (2L * Kseg) + kp0) = *(uint4*)o;
}

__global__ void k_exp_im2col3(const float* __restrict__ src, __nv_bfloat16* __restrict__ dst,
                              int Cin, int logC, int Kseg, int perBatch)
{
    long row = blockIdx.y;
    int b, s; bool rv = true;
    if (perBatch) { b = (int)(row >> 8); int rp = (int)(row & 255); rv = rp < 196; s = rp; }
    else          { b = (int)(row / 196); s = (int)(row % 196); }
    int kp0 = (blockIdx.x * blockDim.x + threadIdx.x) << 3;
    if (kp0 >= 2 * Kseg) return;
    bool lo = kp0 >= Kseg;
    int k = kp0 - (lo ? Kseg : 0);
    float xv[8];
#pragma unroll
    for (int j = 0; j < 8; j++) xv[j] = 0.0f;
    if (rv) {
        int off = k >> logC, c = k & (Cin - 1);
        int yy = s / 14, xx = s - yy * 14;
        int sy = yy + off / 3 - 1, sx = xx + off % 3 - 1;
        if ((unsigned)sy < 14u && (unsigned)sx < 14u) {
            const float* p = src + (((long)(b * 196 + sy * 14 + sx)) << logC) + c;
            float4 f0 = *(const float4*)p, f1 = *(const float4*)(p + 4);
            xv[0]=f0.x; xv[1]=f0.y; xv[2]=f0.z; xv[3]=f0.w;
            xv[4]=f1.x; xv[5]=f1.y; xv[6]=f1.z; xv[7]=f1.w;
        }
    }
    __nv_bfloat16 o[8];
#pragma unroll
    for (int j = 0; j < 8; j++) o[j] = pick_hl(xv[j], lo);
    *(uint4*)(dst + row * (2L * Kseg) + kp0) = *(uint4*)o;
}

__global__ void k_exp_patch(const float* __restrict__ x, __nv_bfloat16* __restrict__ dst)
{
    int row = blockIdx.y;
    int b = row / 196, s = row % 196;
    int ph = s / 14, pw = s - ph * 14;
    int kp0 = (blockIdx.x * blockDim.x + threadIdx.x) << 3;
    if (kp0 >= 1536) return;
    bool lo = kp0 >= 768;
    int k = kp0 - (lo ? 768 : 0);
    int c = k >> 8, ii = (k >> 4) & 15, jj = k & 15;
    const float* p = x + (((long)(b * 3 + c) * 224) + ph * 16 + ii) * 224 + pw * 16 + jj;
    float4 f0 = *(const float4*)p, f1 = *(const float4*)(p + 4);
    float xv[8] = {f0.x, f0.y, f0.z, f0.w, f1.x, f1.y, f1.z, f1.w};
    __nv_bfloat16 o[8];
#pragma unroll
    for (int j = 0; j < 8; j++) o[j] = pick_hl(xv[j], lo);
    *(uint4*)(dst + (long)row * 1536 + kp0) = *(uint4*)o;
}

__global__ void k_exp_w3x3(const float* __restrict__ src, __nv_bfloat16* __restrict__ dst,
                           int Nout, int Cin, int logC, int Kseg)
{
    int n = blockIdx.y;
    int kp0 = (blockIdx.x * blockDim.x + threadIdx.x) << 3;
    if (kp0 >= 2 * Kseg) return;
    bool lo = kp0 >= Kseg;
    int k = kp0 - (lo ? Kseg : 0);
    int off = k >> logC, c = k & (Cin - 1);
    bool inb = (n < Nout);
    __nv_bfloat16 o[8];
#pragma unroll
    for (int j = 0; j < 8; j++) {
        float xx = inb ? src[((long)n * Cin + c + j) * 9 + off] : 0.0f;
        o[j] = pick_hl(xx, lo);
    }
    *(uint4*)(dst + (long)n * (2L * Kseg) + kp0) = *(uint4*)o;
}

// ---------------- FFMA split-K (skinny M=64) ----------------
__device__ __forceinline__ unsigned long long pk2(float a, float b) {
    unsigned long long r;
    asm("mov.b64 %0, {%1, %2};" : "=l"(r) : "f"(a), "f"(b));
    return r;
}
__device__ __forceinline__ void fma2(unsigned long long& d,
                                     unsigned long long a, unsigned long long b) {
    asm("fma.rn.f32x2 %0, %1, %2, %0;" : "+l"(d) : "l"(a), "l"(b));
}
__device__ __forceinline__ float2 up2(unsigned long long v) {
    float a, b;
    asm("mov.b64 {%0, %1}, %2;" : "=f"(a), "=f"(b) : "l"(v));
    return make_float2(a, b);
}

__global__ __launch_bounds__(256) void k_gemm_split(
    const float* __restrict__ A, const float* __restrict__ Bm, float* __restrict__ C,
    int M, int N, int K, int nsplit)
{
    __shared__ __align__(16) float As[16][68];
    __shared__ __align__(16) float Bs[16][68];
    const int z = blockIdx.z;
    int kc = (K + nsplit - 1) / nsplit;
    int kBeg = z * kc, kEnd = min(K, kBeg + kc);
    C += (long)z * M * N;
    const int tid = threadIdx.x;
    const int m0 = blockIdx.y * 64, n0 = blockIdx.x * 64;
    const int tr = tid >> 4, tc = tid & 15;
    unsigned long long acc[4][2];
#pragma unroll
    for (int i = 0; i < 4; i++) { acc[i][0] = 0ULL; acc[i][1] = 0ULL; }
    for (int k0 = kBeg; k0 < kEnd; k0 += 16) {
#pragma unroll
        for (int i = 0; i < 4; i++) {
            int f = tid + i * 256;
            int m = f >> 4, kk = f & 15;
            int gm = m0 + m, gk = k0 + kk;
            As[kk][m] = (gm < M && gk < kEnd) ? A[(long)gm * K + gk] : 0.0f;
            int gn = n0 + m;
            Bs[kk][m] = (gn < N && gk < kEnd) ? Bm[(long)gn * K + gk] : 0.0f;
        }
        __syncthreads();
#pragma unroll
        for (int kk = 0; kk < 16; kk++) {
            float4 av = *(const float4*)&As[kk][tr * 4];
            ulonglong2 bp = *(const ulonglong2*)&Bs[kk][tc * 4];
            unsigned long long a0 = pk2(av.x, av.x), a1 = pk2(av.y, av.y);
            unsigned long long a2 = pk2(av.z, av.z), a3 = pk2(av.w, av.w);
            fma2(acc[0][0], a0, bp.x); fma2(acc[0][1], a0, bp.y);
            fma2(acc[1][0], a1, bp.x); fma2(acc[1][1], a1, bp.y);
            fma2(acc[2][0], a2, bp.x); fma2(acc[2][1], a2, bp.y);
            fma2(acc[3][0], a3, bp.x); fma2(acc[3][1], a3, bp.y);
        }
        __syncthreads();
    }
#pragma unroll
    for (int i = 0; i < 4; i++) {
        int gm = m0 + tr * 4 + i;
        if (gm >= M) continue;
#pragma unroll
        for (int jp = 0; jp < 2; jp++) {
            float2 v = up2(acc[i][jp]);
            int gn = n0 + tc * 4 + jp * 2;
            if (gn < N)     C[(long)gm * N + gn] = v.x;
            if (gn + 1 < N) C[(long)gm * N + gn + 1] = v.y;
        }
    }
}

// ---------------- small kernels ----------------
__global__ void k_softmax(float* __restrict__ sc) {
    long row = blockIdx.x;
    float* p = sc + row * 196;
    int t = threadIdx.x;
    __shared__ float red[256];
    float v = (t < 196) ? p[t] : -3.4e38f;
    red[t] = v; __syncthreads();
    for (int s = 128; s > 0; s >>= 1) { if (t < s) red[t] = fmaxf(red[t], red[t + s]); __syncthreads(); }
    float mx = red[0]; __syncthreads();
    float ex = (t < 196) ? expf(v - mx) : 0.0f;
    red[t] = ex; __syncthreads();
    for (int s = 128; s > 0; s >>= 1) { if (t < s) red[t] += red[t + s]; __syncthreads(); }
    float inv = 1.0f / red[0];
    if (t < 196) p[t] = ex * inv;
}
__global__ void k_bnstat(const float* __restrict__ x, float* __restrict__ psum,
                         float* __restrict__ psq) {
    int c = threadIdx.x, ch = blockIdx.x;
    float s = 0.0f, q = 0.0f;
    long r0 = (long)ch * 196;
    for (int r = 0; r < 196; r++) {
        float v = x[(r0 + r) * 256 + c];
        s += v; q += v * v;
    }
    psum[ch * 256 + c] = s; psq[ch * 256 + c] = q;
}
__global__ void k_bnfin(const float* __restrict__ psum, const float* __restrict__ psq,
                        float* __restrict__ mean, float* __restrict__ istd) {
    int c = threadIdx.x;
    float s = 0.0f, q = 0.0f;
    for (int i = 0; i < 64; i++) { s += psum[i * 256 + c]; q += psq[i * 256 + c]; }
    float m = s / 12544.0f;
    float var = q / 12544.0f - m * m;
    mean[c] = m; istd[c] = rsqrtf(var + 1e-5f);
}
__global__ void k_bnnorm(const float* __restrict__ x, float* __restrict__ out,
                         const float* __restrict__ mean, const float* __restrict__ istd,
                         const float* __restrict__ g, const float* __restrict__ b,
                         int transposed, __nv_bfloat16* __restrict__ hl) {
    long total = ROWS * 256;
    for (long i = blockIdx.x * (long)blockDim.x + threadIdx.x; i < total;
         i += (long)gridDim.x * blockDim.x) {
        int c = (int)(i & 255);
        long row = i >> 8;
        float v = (x[i] - mean[c]) * istd[c] * g[c] + b[c];
        if (!transposed) out[i] = v;
        else {
            int bb = (int)(row / 196), ss = (int)(row % 196);
            out[(long)bb * 50176 + c * 196 + ss] = v;
        }
        if (hl) {
            __nv_bfloat16 hi = __float2bfloat16(v);
            hl[row * 512 + c] = hi;
            hl[row * 512 + 256 + c] = __float2bfloat16(v - __bfloat162float(hi));
        }
    }
}
__global__ void k_tr32(const float* __restrict__ src, float* __restrict__ dst) {
    long total = ROWS * 32;
    for (long i = blockIdx.x * (long)blockDim.x + threadIdx.x; i < total;
         i += (long)gridDim.x * blockDim.x) {
        int b = (int)(i / 6272), r = (int)(i % 6272);
        int c = r / 196, s = r % 196;
        dst[i] = src[((long)(b * 196 + s)) * 32 + c];
    }
}
__global__ void k_reduce(const float* __restrict__ part, float* __restrict__ out,
                         int M, int N, int nsplit, const float* __restrict__ bias, int act) {
    long total = (long)M * N;
    for (long i = blockIdx.x * (long)blockDim.x + threadIdx.x; i < total;
         i += (long)gridDim.x * blockDim.x) {
        int n = (int)(i % N);
        float s = 0.0f;
        for (int p = 0; p < nsplit; p++) s += part[(long)p * total + i];
        if (bias) s += bias[n];
        if (act) s = geluf(s);
        out[i] = s;
    }
}
__global__ void k_rd2(const float* __restrict__ rfc, const float* __restrict__ w,
                      const float* __restrict__ b, int* __restrict__ pos,
                      float* __restrict__ scale) {
    int bb = blockIdx.x, t = threadIdx.x;
    int e = t >> 5, lane = t & 31;
    const float* xr = rfc + (long)bb * 3136;
    const float* wr = w + (long)e * 3136;
    float s = 0.0f;
    for (int k = lane; k < 3136; k += 32) s += xr[k] * wr[k];
    for (int o = 16; o > 0; o >>= 1) s += __shfl_down_sync(0xffffffffu, s, o);
    __shared__ float lg[8];
    if (lane == 0) lg[e] = s + b[e];
    __syncthreads();
    if (t == 0) {
        int best = 0; float bv = lg[0];
        for (int e2 = 1; e2 < 8; e2++) if (lg[e2] > bv) { bv = lg[e2]; best = e2; }
        pos[bb] = best; scale[bb] = bv;
    }
}

// ---------------- host ----------------
static inline int GS(long n) { return (int)((n + 255) / 256); }

static void tgemmP(const __nv_bfloat16* A, const __nv_bfloat16* B, float* part,
                   int M, int Mpad, int N, int Npad, int Kseg, int Z,
                   long sA, long sB, const int* bIdx) {
    cudaFuncSetAttribute(k_tgemmP, cudaFuncAttributeMaxDynamicSharedMemorySize, SMEM_T);
    dim3 g(Npad / 128, Mpad / 128, 3 * Z);
    k_tgemmP<<<g, 256, SMEM_T>>>(A, B, part, M, N, Kseg, sA, sB, (long)M * N, bIdx);
}
static void tgemmF(const __nv_bfloat16* A, const __nv_bfloat16* B,
                   float* C, float* Craw, __nv_bfloat16* CHL,
                   int M, int Mpad, int N, int Npad, int Kseg, int Z,
                   long sA, long sB, long sC, long sCHL,
                   const float* bias, float alpha, int act,
                   const float* addSrc, long sAdd, int addMode) {
    cudaFuncSetAttribute(k_tgemmF, cudaFuncAttributeMaxDynamicSharedMemorySize, SMEM_T);
    dim3 g(Npad / 128, Mpad / 128, Z);
    k_tgemmF<<<g, 256, SMEM_T>>>(A, B, C, Craw, CHL, M, N, Kseg, sA, sB, sC, sCHL,
                                 bias, alpha, act, addSrc, sAdd, addMode);
}
static void redphase(const float* part, float* C, int M, int N, int Z,
                     const int* bIdx, const float* bias, long sBias,
                     const float* zscale, int act,
                     const float* addSrc, long sAdd, int addMode) {
    k_redphase<<<GS((long)Z * M * N), 256>>>(part, C, M, N, Z, bIdx, bias, sBias,
                                             zscale, act, addSrc, sAdd, addMode);
}
static void expand8(const float* src, __nv_bfloat16* dst, int Rvalid, int Rpad,
                    int K, int Kseg, long sSrc, int ld, int trans, int Z) {
    dim3 g((2 * Kseg / 8 + 127) / 128, Z * Rpad);
    k_expand8<<<g, 128>>>(src, dst, Rvalid, Rpad, K, Kseg, sSrc, ld, trans);
}
static void exp_im2col3(const float* src, __nv_bfloat16* dst, int Cin, int logC,
                        int Kseg, int perBatch) {
    dim3 g((2 * Kseg / 8 + 127) / 128, perBatch ? 16384 : 12544);
    k_exp_im2col3<<<g, 128>>>(src, dst, Cin, logC, Kseg, perBatch);
}

extern "C" void kernel_launch(void* const* d_in, const int* in_sizes, int n_in,
                              void* d_out, int out_size) {
    const float* x       = (const float*)d_in[0];
    const float* patch_w = (const float*)d_in[1];
    const float* patch_b = (const float*)d_in[2];
    const float* pos_emb = (const float*)d_in[3];
    const float* wo_w    = (const float*)d_in[4];
    const float* wo_b    = (const float*)d_in[5];
    const float* bn1_g   = (const float*)d_in[6];
    const float* bn1_b   = (const float*)d_in[7];
    const float* rc1_w   = (const float*)d_in[8];
    const float* rc1_b   = (const float*)d_in[9];
    const float* rc2_w   = (const float*)d_in[10];
    const float* rc2_b   = (const float*)d_in[11];
    const float* rc3_w   = (const float*)d_in[12];
    const float* rc3_b   = (const float*)d_in[13];
    const float* rd1_w   = (const float*)d_in[14];
    const float* rd1_b   = (const float*)d_in[15];
    const float* rd2_w   = (const float*)d_in[16];
    const float* rd2_b   = (const float*)d_in[17];
    const float* exp_w1  = (const float*)d_in[18];
    const float* exp_b1  = (const float*)d_in[19];
    const float* exp_w2  = (const float*)d_in[20];
    const float* exp_b2  = (const float*)d_in[21];
    const float* shard_w = (const float*)d_in[22];
    const float* shard_b = (const float*)d_in[23];
    const float* bn2_g   = (const float*)d_in[24];
    const float* bn2_b   = (const float*)d_in[25];
    const float* od1_w   = (const float*)d_in[26];
    const float* od1_b   = (const float*)d_in[27];
    const float* od2_w   = (const float*)d_in[28];
    const float* od2_b   = (const float*)d_in[29];

    float* F = nullptr;            cudaGetSymbolAddress((void**)&F, g_f);
    __nv_bfloat16* Hh = nullptr;   cudaGetSymbolAddress((void**)&Hh, g_h);
    int* posP = nullptr;           cudaGetSymbolAddress((void**)&posP, g_pos);

    float *Y = F + O_Y, *sc = F + O_SC, *re2 = F + O_RE2;
    float *pre1 = F + O_PRE1, *outb = F + O_OUT, *r1 = F + O_R1, *r2 = F + O_R2;
    float *r3 = F + O_R3, *r3t = F + O_R3T, *part = F + O_PART, *rfc = F + O_RFC;
    float *h1 = F + O_H1, *rexp = F + O_REX, *out1 = F + O_OUT1, *ot = F + O_OT;
    float *ofc = F + O_OFC, *bs1 = F + O_BS1, *bs2 = F + O_BS2;
    float *meanp = F + O_MEAN, *istdp = F + O_ISTD, *scalp = F + O_SCAL;

    __nv_bfloat16 *ABig = Hh + B_ABIG, *YAB = Hh + B_YAB, *ATT = Hh + B_ATT;
    __nv_bfloat16 *YT = Hh + B_YT, *REAHL = Hh + B_REAHL, *OUTHL = Hh + B_OUTHL;
    __nv_bfloat16 *PW = Hh + B_PW, *WO = Hh + B_WO, *SH = Hh + B_SH;
    __nv_bfloat16 *RC1 = Hh + B_RC1, *RC2 = Hh + B_RC2, *RC3 = Hh + B_RC3;
    __nv_bfloat16 *EW1 = Hh + B_EW1, *EW2 = Hh + B_EW2;

    const float inv14 = 1.0f / sqrtf(14.0f);

    // launch order: idx 3 = split patch GEMM (profiled)
    expand8(patch_w, PW, 256, 256, 768, 768, 0, 768, 0, 1);            // 0
    { dim3 g(2, 12544); k_exp_patch<<<g, 128>>>(x, ABig); }            // 1
    expand8(wo_w, WO, 256, 256, 256, 256, 0, 256, 0, 1);               // 2
    tgemmP(ABig, PW, part, 12544, 12544, 256, 256, 768, 1, 0, 0, nullptr);  // 3
    redphase(part, Y, 12544, 256, 1, nullptr, patch_b, 0, nullptr, 0, pos_emb, 0, 2);

    expand8(shard_w, SH, 256, 256, 256, 256, 0, 256, 0, 1);
    { dim3 g(5, 128);  k_exp_w3x3<<<g, 128>>>(rc1_w, RC1, 128, 256, 8, 2304); }
    { dim3 g(3, 128);  k_exp_w3x3<<<g, 128>>>(rc2_w, RC2, 64, 128, 7, 1152); }
    { dim3 g(2, 128);  k_exp_w3x3<<<g, 128>>>(rc3_w, RC3, 32, 64, 6, 576); }
    { dim3 g(5, 2048); k_exp_w3x3<<<g, 128>>>(exp_w1, EW1, 2048, 256, 8, 2304); }
    { dim3 g(5, 2048); k_exp_w3x3<<<g, 128>>>(exp_w2, EW2, 2048, 256, 8, 2304); }

    // attention (fused; K too small for split)
    expand8(Y, YAB, 196, 256, 256, 256, 196 * 256, 256, 0, 64);
    tgemmF(YAB, YAB, sc, nullptr, nullptr, 196, 256, 196, 256, 256, 64,
           256L * 512, 256L * 512, 196L * 196, 0, nullptr, inv14, 0, nullptr, 0, 0);
    k_softmax<<<12544, 256>>>(sc);
    expand8(sc, ATT, 196, 256, 196, 256, 196 * 196, 196, 0, 64);
    expand8(Y, YT, 256, 256, 196, 256, 196 * 256, 256, 1, 64);
    tgemmF(ATT, YT, nullptr, nullptr, REAHL, 196, 256, 256, 256, 256, 64,
           256L * 512, 256L * 512, 0, 196L * 512, nullptr, 1.0f, 0, nullptr, 0, 0);
    tgemmF(REAHL, WO, pre1, re2, nullptr, 12544, 12544, 256, 256, 256, 1,
           0, 0, 0, 0, wo_b, 1.0f, 0, Y, 0, 1);

    // bn1 (hi/lo side-output feeds shard GEMM)
    k_bnstat<<<64, 256>>>(pre1, bs1, bs2);
    k_bnfin<<<1, 256>>>(bs1, bs2, meanp, istdp);
    k_bnnorm<<<GS(ROWS * 256), 256>>>(pre1, outb, meanp, istdp, bn1_g, bn1_b, 0, OUTHL);

    // shard shortcut (fused)
    tgemmF(OUTHL, SH, out1, nullptr, nullptr, 12544, 12544, 256, 256, 256, 1,
           0, 0, 0, 0, shard_b, 1.0f, 0, nullptr, 0, 0);

    // router convs (split)
    exp_im2col3(outb, ABig, 256, 8, 2304, 0);
    tgemmP(ABig, RC1, part, 12544, 12544, 128, 128, 2304, 1, 0, 0, nullptr);
    redphase(part, r1, 12544, 128, 1, nullptr, rc1_b, 0, nullptr, 1, nullptr, 0, 0);
    exp_im2col3(r1, ABig, 128, 7, 1152, 0);
    tgemmP(ABig, RC2, part, 12544, 12544, 64, 128, 1152, 1, 0, 0, nullptr);
    redphase(part, r2, 12544, 64, 1, nullptr, rc2_b, 0, nullptr, 1, nullptr, 0, 0);
    exp_im2col3(r2, ABig, 64, 6, 576, 0);
    tgemmP(ABig, RC3, part, 12544, 12544, 32, 128, 576, 1, 0, 0, nullptr);
    redphase(part, r3, 12544, 32, 1, nullptr, rc3_b, 0, nullptr, 1, nullptr, 0, 0);
    k_tr32<<<GS(ROWS * 32), 256>>>(r3, r3t);

    // router dense (FFMA split-K) + argmax gate
    { dim3 g(49, 1, 8); k_gemm_split<<<g, 256>>>(r3t, rd1_w, part, 64, 3136, 6272, 8); }
    k_reduce<<<GS(64L * 3136), 256>>>(part, rfc, 64, 3136, 8, rd1_b, 1);
    k_rd2<<<64, 256>>>(rfc, rd2_w, rd2_b, posP, scalp);

    // experts (split; reduce applies bias+gelu[, gate+out1])
    exp_im2col3(re2, ABig, 256, 8, 2304, 1);
    tgemmP(ABig, EW1, part, 196, 256, 256, 256, 2304, 64,
           256L * 4608, 256L * 4608, posP);
    redphase(part, h1, 196, 256, 64, posP, exp_b1, 256, nullptr, 1, nullptr, 0, 0);
    exp_im2col3(h1, ABig, 256, 8, 2304, 1);
    tgemmP(ABig, EW2, part, 196, 256, 256, 256, 2304, 64,
           256L * 4608, 256L * 4608, posP);
    redphase(part, rexp, 196, 256, 64, posP, exp_b2, 256, scalp, 1,
             out1, 196L * 256, 1);

    // bn2 (transposed write [b][c][s])
    k_bnstat<<<64, 256>>>(rexp, bs1, bs2);
    k_bnfin<<<1, 256>>>(bs1, bs2, meanp, istdp);
    k_bnnorm<<<GS(ROWS * 256), 256>>>(rexp, ot, meanp, istdp, bn2_g, bn2_b, 1, nullptr);

    // output head (FFMA split-K)
    { dim3 g(16, 1, 32); k_gemm_split<<<g, 256>>>(ot, od1_w, part, 64, 1024, 50176, 32); }
    k_reduce<<<GS(64L * 1024), 256>>>(part, ofc, 64, 1024, 32, od1_b, 1);
    { dim3 g(16, 1, 8); k_gemm_split<<<g, 256>>>(ofc, od2_w, part, 64, 1000, 1024, 8); }
    k_reduce<<<GS(64L * 1000), 256>>>(part, (float*)d_out, 64, 1000, 8, od2_b, 0);
}

// round 16
// speedup vs baseline: 1.0915x; 1.0195x over previous
#include <cuda_runtime.h>
#include <cuda_bf16.h>
#include <math.h>
#include <stdint.h>

constexpr int  NB   = 64;
constexpr long ROWS = 12544;

// ---------------- fp32 scratch ----------------
constexpr long O_Y=0, O_SC=O_Y+3211264, O_RE2=O_SC+2458624,
 O_PRE1=O_RE2+3211264, O_OUT=O_PRE1+3211264, O_R1=O_OUT+3211264, O_R2=O_R1+1605632,
 O_R3=O_R2+802816, O_R3T=O_R3+401408, O_PART=O_R3T+401408,
 O_RFC=O_PART+9633792,
 O_H1=O_RFC+200704, O_REX=O_H1+3211264, O_OUT1=O_REX+3211264, O_OT=O_OUT1+3211264,
 O_OFC=O_OT+3211264, O_BS1=O_OFC+65536, O_BS2=O_BS1+16384, O_MEAN=O_BS2+16384,
 O_ISTD=O_MEAN+256, O_SCAL=O_ISTD+256, O_FEND=O_SCAL+64;
__device__ float g_f[O_FEND];
__device__ int   g_pos[64];

// ---------------- bf16 scratch ([hi|lo] 2-segment layouts) ----------------
constexpr long B_ABIG=0;                                    // 16384 x 4608 (router)
constexpr long B_ABIG2= B_ABIG + 75497472L;                 // 16384 x 4608 (experts)
constexpr long B_YAB  = B_ABIG2+ 75497472L;                 // 64 x 256 x 512
constexpr long B_ATT  = B_YAB  + 8388608L;
constexpr long B_YT   = B_ATT  + 8388608L;
constexpr long B_REAHL= B_YT   + 8388608L;                  // 12544 x 512
constexpr long B_OUTHL= B_REAHL+ 6422528L;                  // 12544 x 512
constexpr long B_PW   = B_OUTHL+ 6422528L;                  // 256 x 1536
constexpr long B_WO   = B_PW   + 393216L;
constexpr long B_SH   = B_WO   + 131072L;
constexpr long B_RC1  = B_SH   + 131072L;                   // 128 x 4608
constexpr long B_RC2  = B_RC1  + 589824L;
constexpr long B_RC3  = B_RC2  + 294912L;
constexpr long B_EW1  = B_RC3  + 147456L;                   // 2048 x 4608
constexpr long B_EW2  = B_EW1  + 9437184L;
constexpr long B_HEND = B_EW2  + 9437184L;
__device__ __align__(1024) __nv_bfloat16 g_h[B_HEND];

// ---------------- helpers ----------------
__device__ __forceinline__ uint32_t smem_u32(const void* p) {
    uint32_t a;
    asm("{ .reg .u64 t; cvta.to.shared.u64 t, %1; cvt.u32.u64 %0, t; }" : "=r"(a) : "l"(p));
    return a;
}
__device__ __forceinline__ float geluf(float v) {
    return 0.5f * v * (1.0f + erff(v * 0.70710678118654752440f));
}
#define CP_ASYNC16(dst, src) \
    asm volatile("cp.async.ca.shared.global [%0], [%1], 16;" :: "r"(dst), "l"(src))
#define CP_COMMIT() asm volatile("cp.async.commit_group;" ::: "memory")
#define CP_WAIT1()  asm volatile("cp.async.wait_group 1;" ::: "memory")
#define LDSM_X4(r, addr) \
    asm volatile("ldmatrix.sync.aligned.m8n8.x4.shared.b16 {%0,%1,%2,%3}, [%4];" \
        : "=r"((r)[0]), "=r"((r)[1]), "=r"((r)[2]), "=r"((r)[3]) : "r"(addr))
__device__ __forceinline__ void mma16816(float* c, const uint32_t* a, uint32_t b0, uint32_t b1) {
    asm volatile("mma.sync.aligned.m16n8k16.row.col.f32.bf16.bf16.f32 "
        "{%0,%1,%2,%3}, {%4,%5,%6,%7}, {%8,%9}, {%0,%1,%2,%3};"
        : "+f"(c[0]), "+f"(c[1]), "+f"(c[2]), "+f"(c[3])
        : "r"(a[0]), "r"(a[1]), "r"(a[2]), "r"(a[3]), "r"(b0), "r"(b1));
}
__device__ __forceinline__ __nv_bfloat16 pick_hl(float x, bool lo) {
    __nv_bfloat16 hi = __float2bfloat16(x);
    return lo ? __float2bfloat16(x - __bfloat162float(hi)) : hi;
}

constexpr int SSTR = 40;
constexpr uint32_t BUFB = 128 * SSTR * 2;      // 10240 B
constexpr int SMEM_T = 6 * (int)BUFB;          // 61440

// ---------------- LEAN split GEMM: one phase per CTA, raw partial store ----------------
__global__ __launch_bounds__(256) void k_tgemmP(
    const __nv_bfloat16* __restrict__ A, const __nv_bfloat16* __restrict__ Bm,
    float* __restrict__ C, int M, int N, int Kseg,
    long sA, long sB, long sC,
    const int* __restrict__ bIdx)
{
    extern __shared__ __align__(16) char smem[];
    const int tid = threadIdx.x, w = tid >> 5, lane = tid & 31;
    const int zt = blockIdx.z, m0 = blockIdx.y * 128, n0 = blockIdx.x * 128;
    const int zb = zt / 3, phase = zt - zb * 3;
    const int Ka = 2 * Kseg;

    A += (long)zb * sA;
    const int bi = bIdx ? bIdx[zb] : zb;
    Bm += (long)bi * sB;
    float* Cz = C + (long)zt * sC;

    const uint32_t saB = smem_u32(smem);
    const uint32_t sbB = saB + 3 * BUFB;

    const int wm = w & 3, wn = w >> 2;
    const int matId = lane >> 3;
    const int aRow = wm * 32 + (matId & 1) * 8 + (lane & 7);
    const int aCol = (matId >> 1) * 8;
    const int bRow = wn * 64 + (matId >> 1) * 8 + (lane & 7);
    const int bCol = (matId & 1) * 8;

    float acc[2][8][4];
#pragma unroll
    for (int i = 0; i < 2; i++)
#pragma unroll
        for (int j = 0; j < 8; j++)
#pragma unroll
            for (int e = 0; e < 4; e++) acc[i][j][e] = 0.0f;

    const int nk = Kseg >> 5;
    const int aOffP = (phase == 2) ? Kseg : 0;
    const int bOffP = (phase == 1) ? Kseg : 0;
    const int ldRow  = tid >> 2, ldC8 = (tid & 3) << 3;
    const int ldRow1 = (tid + 256) >> 2;

    auto issue = [&](int within, int buf) {
        const __nv_bfloat16* Ab = A + (long)m0 * Ka + aOffP + (within << 5);
        const __nv_bfloat16* Bb = Bm + (long)n0 * Ka + bOffP + (within << 5);
        const uint32_t bo = (uint32_t)buf * BUFB;
        CP_ASYNC16(saB + bo + (uint32_t)((ldRow  * SSTR + ldC8) * 2), Ab + (long)ldRow  * Ka + ldC8);
        CP_ASYNC16(sbB + bo + (uint32_t)((ldRow  * SSTR + ldC8) * 2), Bb + (long)ldRow  * Ka + ldC8);
        CP_ASYNC16(saB + bo + (uint32_t)((ldRow1 * SSTR + ldC8) * 2), Ab + (long)ldRow1 * Ka + ldC8);
        CP_ASYNC16(sbB + bo + (uint32_t)((ldRow1 * SSTR + ldC8) * 2), Bb + (long)ldRow1 * Ka + ldC8);
        CP_COMMIT();
    };

    issue(0, 0);
    issue(1, 1);
    CP_WAIT1();
    __syncthreads();

    for (int i = 0; i < nk; i++) {
        const int buf = i % 3;
        if (i + 2 < nk) issue(i + 2, (i + 2) % 3);

        const uint32_t sa0 = saB + (uint32_t)buf * BUFB;
        const uint32_t sb0 = sbB + (uint32_t)buf * BUFB;
#pragma unroll
        for (int k16 = 0; k16 < 2; k16++) {
            uint32_t af[2][4];
#pragma unroll
            for (int mi = 0; mi < 2; mi++)
                LDSM_X4(af[mi], sa0 + (uint32_t)((((aRow + mi * 16) * SSTR) + aCol + k16 * 16) * 2));
            uint32_t bf[4][4];
#pragma unroll
            for (int nj = 0; nj < 4; nj++)
                LDSM_X4(bf[nj], sb0 + (uint32_t)((((bRow + nj * 16) * SSTR) + bCol + k16 * 16) * 2));
#pragma unroll
            for (int mi = 0; mi < 2; mi++)
#pragma unroll
                for (int nj = 0; nj < 4; nj++) {
                    mma16816(acc[mi][nj * 2],     af[mi], bf[nj][0], bf[nj][1]);
                    mma16816(acc[mi][nj * 2 + 1], af[mi], bf[nj][2], bf[nj][3]);
                }
        }
        CP_WAIT1();
        __syncthreads();
    }

#pragma unroll
    for (int mi = 0; mi < 2; mi++) {
#pragma unroll
        for (int nj2 = 0; nj2 < 8; nj2++) {
            int row0 = m0 + wm * 32 + mi * 16 + (lane >> 2);
            int col0 = n0 + wn * 64 + nj2 * 8 + (lane & 3) * 2;
#pragma unroll
            for (int half = 0; half < 2; half++) {
                int gm = row0 + half * 8;
                if (gm < M && col0 + 2 <= N) {
                    float2 o;
                    o.x = acc[mi][nj2][half * 2];
                    o.y = acc[mi][nj2][half * 2 + 1];
                    *(float2*)(Cz + (long)gm * N + col0) = o;
                }
            }
        }
    }
}

// ---------------- FUSED GEMM: 3 phases accumulated, full epilogue ----------------
__global__ __launch_bounds__(256) void k_tgemmF(
    const __nv_bfloat16* __restrict__ A, const __nv_bfloat16* __restrict__ Bm,
    float* __restrict__ C, float* __restrict__ Craw, __nv_bfloat16* __restrict__ CHL,
    int M, int N, int Kseg,
    long sA, long sB, long sC, long sCHL,
    const float* __restrict__ bias,
    float alpha, int act,
    const float* __restrict__ addSrc, long sAdd, int addMode)
{
    extern __shared__ __align__(16) char smem[];
    const int tid = threadIdx.x, w = tid >> 5, lane = tid & 31;
    const int z = blockIdx.z, m0 = blockIdx.y * 128, n0 = blockIdx.x * 128;
    const int Ka = 2 * Kseg;

    A += (long)z * sA;
    Bm += (long)z * sB;
    float* Cz  = C    ? C    + (long)z * sC  : nullptr;
    float* Cr  = Craw ? Craw + (long)z * sC  : nullptr;
    __nv_bfloat16* CHz = CHL ? CHL + (long)z * sCHL : nullptr;
    const float* addP = addSrc ? addSrc + (long)z * sAdd : nullptr;

    const uint32_t saB = smem_u32(smem);
    const uint32_t sbB = saB + 3 * BUFB;

    const int wm = w & 3, wn = w >> 2;
    const int matId = lane >> 3;
    const int aRow = wm * 32 + (matId & 1) * 8 + (lane & 7);
    const int aCol = (matId >> 1) * 8;
    const int bRow = wn * 64 + (matId >> 1) * 8 + (lane & 7);
    const int bCol = (matId & 1) * 8;

    float acc[2][8][4];
#pragma unroll
    for (int i = 0; i < 2; i++)
#pragma unroll
        for (int j = 0; j < 8; j++)
#pragma unroll
            for (int e = 0; e < 4; e++) acc[i][j][e] = 0.0f;

    const int nk = Kseg >> 5;
    const int ntot = nk * 3;
    const int ldRow  = tid >> 2, ldC8 = (tid & 3) << 3;
    const int ldRow1 = (tid + 256) >> 2;

    auto issue = [&](int ch, int buf) {
        int ph = (ch >= nk) + (ch >= 2 * nk);
        int within = ch - ph * nk;
        int aOff = (ph == 2) ? Kseg : 0;
        int bOff = (ph == 1) ? Kseg : 0;
        const __nv_bfloat16* Ab = A + (long)m0 * Ka + aOff + (within << 5);
        const __nv_bfloat16* Bb = Bm + (long)n0 * Ka + bOff + (within << 5);
        const uint32_t bo = (uint32_t)buf * BUFB;
        CP_ASYNC16(saB + bo + (uint32_t)((ldRow  * SSTR + ldC8) * 2), Ab + (long)ldRow  * Ka + ldC8);
        CP_ASYNC16(sbB + bo + (uint32_t)((ldRow  * SSTR + ldC8) * 2), Bb + (long)ldRow  * Ka + ldC8);
        CP_ASYNC16(saB + bo + (uint32_t)((ldRow1 * SSTR + ldC8) * 2), Ab + (long)ldRow1 * Ka + ldC8);
        CP_ASYNC16(sbB + bo + (uint32_t)((ldRow1 * SSTR + ldC8) * 2), Bb + (long)ldRow1 * Ka + ldC8);
        CP_COMMIT();
    };

    issue(0, 0);
    issue(1, 1);
    CP_WAIT1();
    __syncthreads();

    for (int i = 0; i < ntot; i++) {
        const int buf = i % 3;
        if (i + 2 < ntot) issue(i + 2, (i + 2) % 3);

        const uint32_t sa0 = saB + (uint32_t)buf * BUFB;
        const uint32_t sb0 = sbB + (uint32_t)buf * BUFB;
#pragma unroll
        for (int k16 = 0; k16 < 2; k16++) {
            uint32_t af[2][4];
#pragma unroll
            for (int mi = 0; mi < 2; mi++)
                LDSM_X4(af[mi], sa0 + (uint32_t)((((aRow + mi * 16) * SSTR) + aCol + k16 * 16) * 2));
            uint32_t bf[4][4];
#pragma unroll
            for (int nj = 0; nj < 4; nj++)
                LDSM_X4(bf[nj], sb0 + (uint32_t)((((bRow + nj * 16) * SSTR) + bCol + k16 * 16) * 2));
#pragma unroll
            for (int mi = 0; mi < 2; mi++)
#pragma unroll
                for (int nj = 0; nj < 4; nj++) {
                    mma16816(acc[mi][nj * 2],     af[mi], bf[nj][0], bf[nj][1]);
                    mma16816(acc[mi][nj * 2 + 1], af[mi], bf[nj][2], bf[nj][3]);
                }
        }
        CP_WAIT1();
        __syncthreads();
    }

#pragma unroll
    for (int mi = 0; mi < 2; mi++) {
#pragma unroll
        for (int nj2 = 0; nj2 < 8; nj2++) {
            int row0 = m0 + wm * 32 + mi * 16 + (lane >> 2);
            int col0 = n0 + wn * 64 + nj2 * 8 + (lane & 3) * 2;
#pragma unroll
            for (int half = 0; half < 2; half++) {
                int gm = row0 + half * 8;
                if (gm < M && col0 + 2 <= N) {
                    float v0 = acc[mi][nj2][half * 2]     * alpha;
                    float v1 = acc[mi][nj2][half * 2 + 1] * alpha;
                    if (bias) { v0 += bias[col0]; v1 += bias[col0 + 1]; }
                    if (act) { v0 = geluf(v0); v1 = geluf(v1); }
                    if (Cr) { float2 rr; rr.x = v0; rr.y = v1;
                              *(float2*)(Cr + (long)gm * N + col0) = rr; }
                    if (addMode == 1) {
                        v0 += addP[(long)gm * N + col0];
                        v1 += addP[(long)gm * N + col0 + 1];
                    }
                    if (Cz) { float2 o; o.x = v0; o.y = v1;
                              *(float2*)(Cz + (long)gm * N + col0) = o; }
                    if (CHz) {
                        __nv_bfloat16 h0 = __float2bfloat16(v0);
                        __nv_bfloat16 h1 = __float2bfloat16(v1);
                        __nv_bfloat16 l0 = __float2bfloat16(v0 - __bfloat162float(h0));
                        __nv_bfloat16 l1 = __float2bfloat16(v1 - __bfloat162float(h1));
                        __nv_bfloat162 hh; hh.x = h0; hh.y = h1;
                        __nv_bfloat162 ll; ll.x = l0; ll.y = l1;
                        *(__nv_bfloat162*)(CHz + (long)gm * 2 * N + col0) = hh;
                        *(__nv_bfloat162*)(CHz + (long)gm * 2 * N + N + col0) = ll;
                    }
                }
            }
        }
    }
}

// ---------------- phase reduce ----------------
__global__ void k_redphase(const float* __restrict__ part, float* __restrict__ C,
                           int M, int N, int Z,
                           const int* __restrict__ bIdx, const float* __restrict__ bias,
                           long sBias, const float* __restrict__ zscale, int act,
                           const float* __restrict__ addSrc, long sAdd, int addMode)
{
    long per = (long)M * N;
    long total = (long)Z * per;
    for (long i = blockIdx.x * (long)blockDim.x + threadIdx.x; i < total;
         i += (long)gridDim.x * blockDim.x) {
        int z = (int)(i / per);
        long r = i - (long)z * per;
        int n = (int)(r % N);
        const float* p = part + (long)z * 3 * per + r;
        float v = p[0] + p[per] + p[2 * per];
        if (bias) {
            int bi = bIdx ? bIdx[z] : z;
            v += bias[(long)bi * sBias + n];
        }
        if (act) v = geluf(v);
        if (zscale) v *= zscale[z];
        if (addMode == 1) v += addSrc[(long)z * sAdd + r];
        else if (addMode == 2) {
            int row = (int)(r / N);
            v += addSrc[(long)(row % 196) * N + n];
        }
        C[i] = v;
    }
}

// ---------------- bf16 hi/lo expansion kernels ----------------
__global__ void k_expand8(const float* __restrict__ src, __nv_bfloat16* __restrict__ dst,
                          int Rvalid, int Rpad, int K, int Kseg, long sSrc, int ld, int trans)
{
    long zr = blockIdx.y;
    int r = (int)(zr % Rpad), z = (int)(zr / Rpad);
    int kp0 = (blockIdx.x * blockDim.x + threadIdx.x) << 3;
    if (kp0 >= 2 * Kseg) return;
    bool lo = kp0 >= Kseg;
    int k0 = kp0 - (lo ? Kseg : 0);
    const float* sp = src + (long)z * sSrc;
    __nv_bfloat16 o[8];
#pragma unroll
    for (int j = 0; j < 8; j++) {
        int k = k0 + j;
        float x = 0.0f;
        if (r < Rvalid && k < K)
            x = trans ? sp[(long)k * ld + r] : sp[(long)r * ld + k];
        o[j] = pick_hl(x, lo);
    }
    *(uint4*)(dst + zr * (2L * Kseg) + kp0) = *(uint4*)o;
}

__global__ void k_exp_im2col3(const float* __restrict__ src, __nv_bfloat16* __restrict__ dst,
                              int Cin, int logC, int Kseg, int perBatch)
{
    long row = blockIdx.y;
    int b, s; bool rv = true;
    if (perBatch) { b = (int)(row >> 8); int rp = (int)(row & 255); rv = rp < 196; s = rp; }
    else          { b = (int)(row / 196); s = (int)(row % 196); }
    int kp0 = (blockIdx.x * blockDim.x + threadIdx.x) << 3;
    if (kp0 >= 2 * Kseg) return;
    bool lo = kp0 >= Kseg;
    int k = kp0 - (lo ? Kseg : 0);
    float xv[8];
#pragma unroll
    for (int j = 0; j < 8; j++) xv[j] = 0.0f;
    if (rv) {
        int off = k >> logC, c = k & (Cin - 1);
        int yy = s / 14, xx = s - yy * 14;
        int sy = yy + off / 3 - 1, sx = xx + off % 3 - 1;
        if ((unsigned)sy < 14u && (unsigned)sx < 14u) {
            const float* p = src + (((long)(b * 196 + sy * 14 + sx)) << logC) + c;
            float4 f0 = *(const float4*)p, f1 = *(const float4*)(p + 4);
            xv[0]=f0.x; xv[1]=f0.y; xv[2]=f0.z; xv[3]=f0.w;
            xv[4]=f1.x; xv[5]=f1.y; xv[6]=f1.z; xv[7]=f1.w;
        }
    }
    __nv_bfloat16 o[8];
#pragma unroll
    for (int j = 0; j < 8; j++) o[j] = pick_hl(xv[j], lo);
    *(uint4*)(dst + row * (2L * Kseg) + kp0) = *(uint4*)o;
}

__global__ void k_exp_patch(const float* __restrict__ x, __nv_bfloat16* __restrict__ dst)
{
    int row = blockIdx.y;
    int b = row / 196, s = row % 196;
    int ph = s / 14, pw = s - ph * 14;
    int kp0 = (blockIdx.x * blockDim.x + threadIdx.x) << 3;
    if (kp0 >= 1536) return;
    bool lo = kp0 >= 768;
    int k = kp0 - (lo ? 768 : 0);
    int c = k >> 8, ii = (k >> 4) & 15, jj = k & 15;
    const float* p = x + (((long)(b * 3 + c) * 224) + ph * 16 + ii) * 224 + pw * 16 + jj;
    float4 f0 = *(const float4*)p, f1 = *(const float4*)(p + 4);
    float xv[8] = {f0.x, f0.y, f0.z, f0.w, f1.x, f1.y, f1.z, f1.w};
    __nv_bfloat16 o[8];
#pragma unroll
    for (int j = 0; j < 8; j++) o[j] = pick_hl(xv[j], lo);
    *(uint4*)(dst + (long)row * 1536 + kp0) = *(uint4*)o;
}

__global__ void k_exp_w3x3(const float* __restrict__ src, __nv_bfloat16* __restrict__ dst,
                           int Nout, int Cin, int logC, int Kseg)
{
    int n = blockIdx.y;
    int kp0 = (blockIdx.x * blockDim.x + threadIdx.x) << 3;
    if (kp0 >= 2 * Kseg) return;
    bool lo = kp0 >= Kseg;
    int k = kp0 - (lo ? Kseg : 0);
    int off = k >> logC, c = k & (Cin - 1);
    bool inb = (n < Nout);
    __nv_bfloat16 o[8];
#pragma unroll
    for (int j = 0; j < 8; j++) {
        float xx = inb ? src[((long)n * Cin + c + j) * 9 + off] : 0.0f;
        o[j] = pick_hl(xx, lo);
    }
    *(uint4*)(dst + (long)n * (2L * Kseg) + kp0) = *(uint4*)o;
}

// ---------------- FFMA split-K (skinny M=64) ----------------
__device__ __forceinline__ unsigned long long pk2(float a, float b) {
    unsigned long long r;
    asm("mov.b64 %0, {%1, %2};" : "=l"(r) : "f"(a), "f"(b));
    return r;
}
__device__ __forceinline__ void fma2(unsigned long long& d,
                                     unsigned long long a, unsigned long long b) {
    asm("fma.rn.f32x2 %0, %1, %2, %0;" : "+l"(d) : "l"(a), "l"(b));
}
__device__ __forceinline__ float2 up2(unsigned long long v) {
    float a, b;
    asm("mov.b64 {%0, %1}, %2;" : "=f"(a), "=f"(b) : "l"(v));
    return make_float2(a, b);
}

__global__ __launch_bounds__(256) void k_gemm_split(
    const float* __restrict__ A, const float* __restrict__ Bm, float* __restrict__ C,
    int M, int N, int K, int nsplit)
{
    __shared__ __align__(16) float As[16][68];
    __shared__ __align__(16) float Bs[16][68];
    const int z = blockIdx.z;
    int kc = (K + nsplit - 1) / nsplit;
    int kBeg = z * kc, kEnd = min(K, kBeg + kc);
    C += (long)z * M * N;
    const int tid = threadIdx.x;
    const int m0 = blockIdx.y * 64, n0 = blockIdx.x * 64;
    const int tr = tid >> 4, tc = tid & 15;
    unsigned long long acc[4][2];
#pragma unroll
    for (int i = 0; i < 4; i++) { acc[i][0] = 0ULL; acc[i][1] = 0ULL; }
    for (int k0 = kBeg; k0 < kEnd; k0 += 16) {
#pragma unroll
        for (int i = 0; i < 4; i++) {
            int f = tid + i * 256;
            int m = f >> 4, kk = f & 15;
            int gm = m0 + m, gk = k0 + kk;
            As[kk][m] = (gm < M && gk < kEnd) ? A[(long)gm * K + gk] : 0.0f;
            int gn = n0 + m;
            Bs[kk][m] = (gn < N && gk < kEnd) ? Bm[(long)gn * K + gk] : 0.0f;
        }
        __syncthreads();
#pragma unroll
        for (int kk = 0; kk < 16; kk++) {
            float4 av = *(const float4*)&As[kk][tr * 4];
            ulonglong2 bp = *(const ulonglong2*)&Bs[kk][tc * 4];
            unsigned long long a0 = pk2(av.x, av.x), a1 = pk2(av.y, av.y);
            unsigned long long a2 = pk2(av.z, av.z), a3 = pk2(av.w, av.w);
            fma2(acc[0][0], a0, bp.x); fma2(acc[0][1], a0, bp.y);
            fma2(acc[1][0], a1, bp.x); fma2(acc[1][1], a1, bp.y);
            fma2(acc[2][0], a2, bp.x); fma2(acc[2][1], a2, bp.y);
            fma2(acc[3][0], a3, bp.x); fma2(acc[3][1], a3, bp.y);
        }
        __syncthreads();
    }
#pragma unroll
    for (int i = 0; i < 4; i++) {
        int gm = m0 + tr * 4 + i;
        if (gm >= M) continue;
#pragma unroll
        for (int jp = 0; jp < 2; jp++) {
            float2 v = up2(acc[i][jp]);
            int gn = n0 + tc * 4 + jp * 2;
            if (gn < N)     C[(long)gm * N + gn] = v.x;
            if (gn + 1 < N) C[(long)gm * N + gn + 1] = v.y;
        }
    }
}

// ---------------- small kernels ----------------
__global__ void k_softmax(float* __restrict__ sc) {
    long row = blockIdx.x;
    float* p = sc + row * 196;
    int t = threadIdx.x;
    __shared__ float red[256];
    float v = (t < 196) ? p[t] : -3.4e38f;
    red[t] = v; __syncthreads();
    for (int s = 128; s > 0; s >>= 1) { if (t < s) red[t] = fmaxf(red[t], red[t + s]); __syncthreads(); }
    float mx = red[0]; __syncthreads();
    float ex = (t < 196) ? expf(v - mx) : 0.0f;
    red[t] = ex; __syncthreads();
    for (int s = 128; s > 0; s >>= 1) { if (t < s) red[t] += red[t + s]; __syncthreads(); }
    float inv = 1.0f / red[0];
    if (t < 196) p[t] = ex * inv;
}
__global__ void k_bnstat(const float* __restrict__ x, float* __restrict__ psum,
                         float* __restrict__ psq) {
    int c = threadIdx.x, ch = blockIdx.x;
    float s = 0.0f, q = 0.0f;
    long r0 = (long)ch * 196;
    for (int r = 0; r < 196; r++) {
        float v = x[(r0 + r) * 256 + c];
        s += v; q += v * v;
    }
    psum[ch * 256 + c] = s; psq[ch * 256 + c] = q;
}
__global__ void k_bnfin(const float* __restrict__ psum, const float* __restrict__ psq,
                        float* __restrict__ mean, float* __restrict__ istd) {
    int c = threadIdx.x;
    float s = 0.0f, q = 0.0f;
    for (int i = 0; i < 64; i++) { s += psum[i * 256 + c]; q += psq[i * 256 + c]; }
    float m = s / 12544.0f;
    float var = q / 12544.0f - m * m;
    mean[c] = m; istd[c] = rsqrtf(var + 1e-5f);
}
__global__ void k_bnnorm(const float* __restrict__ x, float* __restrict__ out,
                         const float* __restrict__ mean, const float* __restrict__ istd,
                         const float* __restrict__ g, const float* __restrict__ b,
                         int transposed, __nv_bfloat16* __restrict__ hl) {
    long total = ROWS * 256;
    for (long i = blockIdx.x * (long)blockDim.x + threadIdx.x; i < total;
         i += (long)gridDim.x * blockDim.x) {
        int c = (int)(i & 255);
        long row = i >> 8;
        float v = (x[i] - mean[c]) * istd[c] * g[c] + b[c];
        if (!transposed) out[i] = v;
        else {
            int bb = (int)(row / 196), ss = (int)(row % 196);
            out[(long)bb * 50176 + c * 196 + ss] = v;
        }
        if (hl) {
            __nv_bfloat16 hi = __float2bfloat16(v);
            hl[row * 512 + c] = hi;
            hl[row * 512 + 256 + c] = __float2bfloat16(v - __bfloat162float(hi));
        }
    }
}
__global__ void k_tr32(const float* __restrict__ src, float* __restrict__ dst) {
    long total = ROWS * 32;
    for (long i = blockIdx.x * (long)blockDim.x + threadIdx.x; i < total;
         i += (long)gridDim.x * blockDim.x) {
        int b = (int)(i / 6272), r = (int)(i % 6272);
        int c = r / 196, s = r % 196;
        dst[i] = src[((long)(b * 196 + s)) * 32 + c];
    }
}
__global__ void k_reduce(const float* __restrict__ part, float* __restrict__ out,
                         int M, int N, int nsplit, const float* __restrict__ bias, int act) {
    long total = (long)M * N;
    for (long i = blockIdx.x * (long)blockDim.x + threadIdx.x; i < total;
         i += (long)gridDim.x * blockDim.x) {
        int n = (int)(i % N);
        float s = 0.0f;
        for (int p = 0; p < nsplit; p++) s += part[(long)p * total + i];
        if (bias) s += bias[n];
        if (act) s = geluf(s);
        out[i] = s;
    }
}
__global__ void k_rd2(const float* __restrict__ rfc, const float* __restrict__ w,
                      const float* __restrict__ b, int* __restrict__ pos,
                      float* __restrict__ scale) {
    int bb = blockIdx.x, t = threadIdx.x;
    int e = t >> 5, lane = t & 31;
    const float* xr = rfc + (long)bb * 3136;
    const float* wr = w + (long)e * 3136;
    float s = 0.0f;
    for (int k = lane; k < 3136; k += 32) s += xr[k] * wr[k];
    for (int o = 16; o > 0; o >>= 1) s += __shfl_down_sync(0xffffffffu, s, o);
    __shared__ float lg[8];
    if (lane == 0) lg[e] = s + b[e];
    __syncthreads();
    if (t == 0) {
        int best = 0; float bv = lg[0];
        for (int e2 = 1; e2 < 8; e2++) if (lg[e2] > bv) { bv = lg[e2]; best = e2; }
        pos[bb] = best; scale[bb] = bv;
    }
}

// ---------------- host ----------------
static inline int GS(long n) { return (int)((n + 255) / 256); }

static void tgemmP(const __nv_bfloat16* A, const __nv_bfloat16* B, float* part,
                   int M, int Mpad, int N, int Npad, int Kseg, int Z,
                   long sA, long sB, const int* bIdx, cudaStream_t st) {
    cudaFuncSetAttribute(k_tgemmP, cudaFuncAttributeMaxDynamicSharedMemorySize, SMEM_T);
    dim3 g(Npad / 128, Mpad / 128, 3 * Z);
    k_tgemmP<<<g, 256, SMEM_T, st>>>(A, B, part, M, N, Kseg, sA, sB, (long)M * N, bIdx);
}
static void tgemmF(const __nv_bfloat16* A, const __nv_bfloat16* B,
                   float* C, float* Craw, __nv_bfloat16* CHL,
                   int M, int Mpad, int N, int Npad, int Kseg, int Z,
                   long sA, long sB, long sC, long sCHL,
                   const float* bias, float alpha, int act,
                   const float* addSrc, long sAdd, int addMode, cudaStream_t st) {
    cudaFuncSetAttribute(k_tgemmF, cudaFuncAttributeMaxDynamicSharedMemorySize, SMEM_T);
    dim3 g(Npad / 128, Mpad / 128, Z);
    k_tgemmF<<<g, 256, SMEM_T, st>>>(A, B, C, Craw, CHL, M, N, Kseg, sA, sB, sC, sCHL,
                                     bias, alpha, act, addSrc, sAdd, addMode);
}
static void redphase(const float* part, float* C, int M, int N, int Z,
                     const int* bIdx, const float* bias, long sBias,
                     const float* zscale, int act,
                     const float* addSrc, long sAdd, int addMode, cudaStream_t st) {
    k_redphase<<<GS((long)Z * M * N), 256, 0, st>>>(part, C, M, N, Z, bIdx, bias, sBias,
                                                    zscale, act, addSrc, sAdd, addMode);
}
static void expand8(const float* src, __nv_bfloat16* dst, int Rvalid, int Rpad,
                    int K, int Kseg, long sSrc, int ld, int trans, int Z, cudaStream_t st) {
    dim3 g((2 * Kseg / 8 + 127) / 128, Z * Rpad);
    k_expand8<<<g, 128, 0, st>>>(src, dst, Rvalid, Rpad, K, Kseg, sSrc, ld, trans);
}
static void exp_im2col3(const float* src, __nv_bfloat16* dst, int Cin, int logC,
                        int Kseg, int perBatch, cudaStream_t st) {
    dim3 g((2 * Kseg / 8 + 127) / 128, perBatch ? 16384 : 12544);
    k_exp_im2col3<<<g, 128, 0, st>>>(src, dst, Cin, logC, Kseg, perBatch);
}

extern "C" void kernel_launch(void* const* d_in, const int* in_sizes, int n_in,
                              void* d_out, int out_size) {
    const float* x       = (const float*)d_in[0];
    const float* patch_w = (const float*)d_in[1];
    const float* patch_b = (const float*)d_in[2];
    const float* pos_emb = (const float*)d_in[3];
    const float* wo_w    = (const float*)d_in[4];
    const float* wo_b    = (const float*)d_in[5];
    const float* bn1_g   = (const float*)d_in[6];
    const float* bn1_b   = (const float*)d_in[7];
    const float* rc1_w   = (const float*)d_in[8];
    const float* rc1_b   = (const float*)d_in[9];
    const float* rc2_w   = (const float*)d_in[10];
    const float* rc2_b   = (const float*)d_in[11];
    const float* rc3_w   = (const float*)d_in[12];
    const float* rc3_b   = (const float*)d_in[13];
    const float* rd1_w   = (const float*)d_in[14];
    const float* rd1_b   = (const float*)d_in[15];
    const float* rd2_w   = (const float*)d_in[16];
    const float* rd2_b   = (const float*)d_in[17];
    const float* exp_w1  = (const float*)d_in[18];
    const float* exp_b1  = (const float*)d_in[19];
    const float* exp_w2  = (const float*)d_in[20];
    const float* exp_b2  = (const float*)d_in[21];
    const float* shard_w = (const float*)d_in[22];
    const float* shard_b = (const float*)d_in[23];
    const float* bn2_g   = (const float*)d_in[24];
    const float* bn2_b   = (const float*)d_in[25];
    const float* od1_w   = (const float*)d_in[26];
    const float* od1_b   = (const float*)d_in[27];
    const float* od2_w   = (const float*)d_in[28];
    const float* od2_b   = (const float*)d_in[29];

    float* F = nullptr;            cudaGetSymbolAddress((void**)&F, g_f);
    __nv_bfloat16* Hh = nullptr;   cudaGetSymbolAddress((void**)&Hh, g_h);
    int* posP = nullptr;           cudaGetSymbolAddress((void**)&posP, g_pos);

    float *Y = F + O_Y, *sc = F + O_SC, *re2 = F + O_RE2;
    float *pre1 = F + O_PRE1, *outb = F + O_OUT, *r1 = F + O_R1, *r2 = F + O_R2;
    float *r3 = F + O_R3, *r3t = F + O_R3T, *part = F + O_PART, *rfc = F + O_RFC;
    float *h1 = F + O_H1, *rexp = F + O_REX, *out1 = F + O_OUT1, *ot = F + O_OT;
    float *ofc = F + O_OFC, *bs1 = F + O_BS1, *bs2 = F + O_BS2;
    float *meanp = F + O_MEAN, *istdp = F + O_ISTD, *scalp = F + O_SCAL;

    __nv_bfloat16 *ABig = Hh + B_ABIG, *ABig2 = Hh + B_ABIG2;
    __nv_bfloat16 *YAB = Hh + B_YAB, *ATT = Hh + B_ATT, *YT = Hh + B_YT;
    __nv_bfloat16 *REAHL = Hh + B_REAHL, *OUTHL = Hh + B_OUTHL;
    __nv_bfloat16 *PW = Hh + B_PW, *WO = Hh + B_WO, *SH = Hh + B_SH;
    __nv_bfloat16 *RC1 = Hh + B_RC1, *RC2 = Hh + B_RC2, *RC3 = Hh + B_RC3;
    __nv_bfloat16 *EW1 = Hh + B_EW1, *EW2 = Hh + B_EW2;

    const float inv14 = 1.0f / sqrtf(14.0f);
    const cudaStream_t s0 = 0;

    cudaStream_t s2;
    cudaStreamCreate(&s2);
    cudaEvent_t e0, eW, eBn1, eRouter;
    cudaEventCreateWithFlags(&e0, cudaEventDisableTiming);
    cudaEventCreateWithFlags(&eW, cudaEventDisableTiming);
    cudaEventCreateWithFlags(&eBn1, cudaEventDisableTiming);
    cudaEventCreateWithFlags(&eRouter, cudaEventDisableTiming);

    // ---- default stream: patch chain start ----
    expand8(patch_w, PW, 256, 256, 768, 768, 0, 768, 0, 1, s0);        // 0
    { dim3 g(2, 12544); k_exp_patch<<<g, 128, 0, s0>>>(x, ABig); }     // 1
    expand8(wo_w, WO, 256, 256, 256, 256, 0, 256, 0, 1, s0);           // 2
    cudaEventRecord(e0, s0);

    // ---- s2 branch A: remaining weight expansions ----
    cudaStreamWaitEvent(s2, e0, 0);
    expand8(shard_w, SH, 256, 256, 256, 256, 0, 256, 0, 1, s2);
    { dim3 g(5, 128);  k_exp_w3x3<<<g, 128, 0, s2>>>(rc1_w, RC1, 128, 256, 8, 2304); }
    { dim3 g(3, 128);  k_exp_w3x3<<<g, 128, 0, s2>>>(rc2_w, RC2, 64, 128, 7, 1152); }
    { dim3 g(2, 128);  k_exp_w3x3<<<g, 128, 0, s2>>>(rc3_w, RC3, 32, 64, 6, 576); }
    { dim3 g(5, 2048); k_exp_w3x3<<<g, 128, 0, s2>>>(exp_w1, EW1, 2048, 256, 8, 2304); }
    { dim3 g(5, 2048); k_exp_w3x3<<<g, 128, 0, s2>>>(exp_w2, EW2, 2048, 256, 8, 2304); }
    cudaEventRecord(eW, s2);

    // ---- default: patch GEMM (idx 3) + attention chain ----
    tgemmP(ABig, PW, part, 12544, 12544, 256, 256, 768, 1, 0, 0, nullptr, s0);   // 3
    redphase(part, Y, 12544, 256, 1, nullptr, patch_b, 0, nullptr, 0, pos_emb, 0, 2, s0);
    expand8(Y, YAB, 196, 256, 256, 256, 196 * 256, 256, 0, 64, s0);
    tgemmF(YAB, YAB, sc, nullptr, nullptr, 196, 256, 196, 256, 256, 64,
           256L * 512, 256L * 512, 196L * 196, 0, nullptr, inv14, 0, nullptr, 0, 0, s0);
    k_softmax<<<12544, 256, 0, s0>>>(sc);
    expand8(sc, ATT, 196, 256, 196, 256, 196 * 196, 196, 0, 64, s0);
    expand8(Y, YT, 256, 256, 196, 256, 196 * 256, 256, 1, 64, s0);
    tgemmF(ATT, YT, nullptr, nullptr, REAHL, 196, 256, 256, 256, 256, 64,
           256L * 512, 256L * 512, 0, 196L * 512, nullptr, 1.0f, 0, nullptr, 0, 0, s0);
    tgemmF(REAHL, WO, pre1, re2, nullptr, 12544, 12544, 256, 256, 256, 1,
           0, 0, 0, 0, wo_b, 1.0f, 0, Y, 0, 1, s0);

    // bn1
    k_bnstat<<<64, 256, 0, s0>>>(pre1, bs1, bs2);
    k_bnfin<<<1, 256, 0, s0>>>(bs1, bs2, meanp, istdp);
    k_bnnorm<<<GS(ROWS * 256), 256, 0, s0>>>(pre1, outb, meanp, istdp, bn1_g, bn1_b, 0, OUTHL);
    cudaEventRecord(eBn1, s0);

    // ---- s2 branch B: router chain (uses ABig) ----
    cudaStreamWaitEvent(s2, eBn1, 0);
    exp_im2col3(outb, ABig, 256, 8, 2304, 0, s2);
    tgemmP(ABig, RC1, part, 12544, 12544, 128, 128, 2304, 1, 0, 0, nullptr, s2);
    redphase(part, r1, 12544, 128, 1, nullptr, rc1_b, 0, nullptr, 1, nullptr, 0, 0, s2);
    exp_im2col3(r1, ABig, 128, 7, 1152, 0, s2);
    tgemmP(ABig, RC2, part, 12544, 12544, 64, 128, 1152, 1, 0, 0, nullptr, s2);
    redphase(part, r2, 12544, 64, 1, nullptr, rc2_b, 0, nullptr, 1, nullptr, 0, 0, s2);
    exp_im2col3(r2, ABig, 64, 6, 576, 0, s2);
    tgemmP(ABig, RC3, part, 12544, 12544, 32, 128, 576, 1, 0, 0, nullptr, s2);
    redphase(part, r3, 12544, 32, 1, nullptr, rc3_b, 0, nullptr, 1, nullptr, 0, 0, s2);
    k_tr32<<<GS(ROWS * 32), 256, 0, s2>>>(r3, r3t);
    { dim3 g(49, 1, 8); k_gemm_split<<<g, 256, 0, s2>>>(r3t, rd1_w, part, 64, 3136, 6272, 8); }
    k_reduce<<<GS(64L * 3136), 256, 0, s2>>>(part, rfc, 64, 3136, 8, rd1_b, 1);
    k_rd2<<<64, 256, 0, s2>>>(rfc, rd2_w, rd2_b, posP, scalp);
    cudaEventRecord(eRouter, s2);

    // ---- default: shard + expert-1 im2col, concurrent with router ----
    cudaStreamWaitEvent(s0, eW, 0);
    tgemmF(OUTHL, SH, out1, nullptr, nullptr, 12544, 12544, 256, 256, 256, 1,
           0, 0, 0, 0, shard_b, 1.0f, 0, nullptr, 0, 0, s0);
    exp_im2col3(re2, ABig2, 256, 8, 2304, 1, s0);

    // ---- join: experts need posP/scalp ----
    cudaStreamWaitEvent(s0, eRouter, 0);
    tgemmP(ABig2, EW1, part, 196, 256, 256, 256, 2304, 64,
           256L * 4608, 256L * 4608, posP, s0);
    redphase(part, h1, 196, 256, 64, posP, exp_b1, 256, nullptr, 1, nullptr, 0, 0, s0);
    exp_im2col3(h1, ABig2, 256, 8, 2304, 1, s0);
    tgemmP(ABig2, EW2, part, 196, 256, 256, 256, 2304, 64,
           256L * 4608, 256L * 4608, posP, s0);
    redphase(part, rexp, 196, 256, 64, posP, exp_b2, 256, scalp, 1,
             out1, 196L * 256, 1, s0);

    // bn2 (transposed write [b][c][s])
    k_bnstat<<<64, 256, 0, s0>>>(rexp, bs1, bs2);
    k_bnfin<<<1, 256, 0, s0>>>(bs1, bs2, meanp, istdp);
    k_bnnorm<<<GS(ROWS * 256), 256, 0, s0>>>(rexp, ot, meanp, istdp, bn2_g, bn2_b, 1, nullptr);

    // output head (FFMA split-K)
    { dim3 g(16, 1, 32); k_gemm_split<<<g, 256, 0, s0>>>(ot, od1_w, part, 64, 1024, 50176, 32); }
    k_reduce<<<GS(64L * 1024), 256, 0, s0>>>(part, ofc, 64, 1024, 32, od1_b, 1);
    { dim3 g(16, 1, 8); k_gemm_split<<<g, 256, 0, s0>>>(ofc, od2_w, part, 64, 1000, 1024, 8); }
    k_reduce<<<GS(64L * 1000), 256, 0, s0>>>(part, (float*)d_out, 64, 1000, 8, od2_b, 0);
    // streams/events intentionally not destroyed during capture (host objects, tiny)
}